// round 12
// baseline (speedup 1.0000x reference)
#include <cuda_runtime.h>
#include <cuda_fp16.h>

#define NMAX 100000
#define EMAX 1600000
#define F1 128
#define F2 64
#define BN_EPS 1e-5f
#define SCAN_B 1024
#define BN_GRID 1024

// ---- scratch (device globals; zero-initialized at load; no allocation) ----
__device__ float  g_dis[NMAX];             // rsqrt(degree)
__device__ int    g_degi[NMAX];            // in-degree (zeroed by agg2 restore)
__device__ int    g_row[NMAX];             // CSR row start
__device__ int    g_epos[EMAX];            // per-edge rank within destination
__device__ int    g_rowtmp[NMAX];          // block-local exclusive scan
__device__ int    g_bsum[128];             // scan block sums
__device__ int    g_csr[EMAX];             // src indices grouped by dst
__device__ uint4  g_H1h[NMAX * 16];        // fp16 dis*(x@W1^T)        [N,128]
__device__ uint4  g_A1h[NMAX * 16];        // fp16 layer-1 aggregated  [N,128]
__device__ uint4  g_H2h[NMAX * 8];         // fp16 dis*(relu(bn)@W2^T) [N,64]
__device__ float  g_sums[2 * F1];          // BN sum/sumsq (zero-restored)
__device__ uint4  g_W1h4[F1 * F1 / 8];     // fp16 W1 row-major [c][k]; 64 uints/row
__device__ uint4  g_W2h4[F1 * F2 / 8];     // fp16 W2 row-major [c][k]; 64 uints/row

// ---- fp16 mma m16n8k16 (row.col, f32 accum) ----
__device__ __forceinline__ void mma_f16(float* d, const unsigned* a, const unsigned* b) {
    asm volatile(
        "mma.sync.aligned.m16n8k16.row.col.f32.f16.f16.f32 "
        "{%0,%1,%2,%3}, {%4,%5,%6,%7}, {%8,%9}, {%0,%1,%2,%3};"
        : "+f"(d[0]), "+f"(d[1]), "+f"(d[2]), "+f"(d[3])
        : "r"(a[0]), "r"(a[1]), "r"(a[2]), "r"(a[3]), "r"(b[0]), "r"(b[1]));
}

__device__ __forceinline__ unsigned pack_half2(float a, float b) {
    __half2 h = __floats2half2_rn(a, b);
    return *reinterpret_cast<unsigned*>(&h);
}

// fp16 row accumulate: acc[0..7] += unpack(u)
__device__ __forceinline__ void acc_u4(float* acc, uint4 u) {
    float2 f0 = __half22float2(*(__half2*)&u.x);
    float2 f1 = __half22float2(*(__half2*)&u.y);
    float2 f2 = __half22float2(*(__half2*)&u.z);
    float2 f3 = __half22float2(*(__half2*)&u.w);
    acc[0] += f0.x; acc[1] += f0.y;
    acc[2] += f1.x; acc[3] += f1.y;
    acc[4] += f2.x; acc[5] += f2.y;
    acc[6] += f3.x; acc[7] += f3.y;
}

// ---------------------------------------------------------------------------
// degree count + per-edge rank; also converts weights to fp16
// ---------------------------------------------------------------------------
__global__ void k_deg_count(const int* __restrict__ ei,
                            const float* __restrict__ W1,
                            const float* __restrict__ W2, int e_cnt) {
    int e = blockIdx.x * blockDim.x + threadIdx.x;
    if (e < F1 * F1) ((__half*)g_W1h4)[e] = __float2half_rn(W1[e]);
    if (e < F1 * F2) ((__half*)g_W2h4)[e] = __float2half_rn(W2[e]);
    if (e < e_cnt) {
        int d = ei[e_cnt + e];
        g_epos[e] = atomicAdd(&g_degi[d], 1);
    }
}

// ---------------------------------------------------------------------------
// scan (2 stages, proven): block-exclusive -> finalize
// ---------------------------------------------------------------------------
__global__ void __launch_bounds__(SCAN_B) k_scan_block(int n) {
    __shared__ int s[SCAN_B];
    int t = threadIdx.x;
    int i = blockIdx.x * SCAN_B + t;
    int v = (i < n) ? g_degi[i] : 0;
    s[t] = v;
    __syncthreads();
    for (int off = 1; off < SCAN_B; off <<= 1) {
        int a = (t >= off) ? s[t - off] : 0;
        __syncthreads();
        s[t] += a;
        __syncthreads();
    }
    if (i < n) g_rowtmp[i] = s[t] - v;
    if (t == SCAN_B - 1) g_bsum[blockIdx.x] = s[t];
}

__global__ void __launch_bounds__(SCAN_B) k_scan_fin(int n, int nb) {
    __shared__ int wsum[32];
    int t = threadIdx.x;
    int v = (t < nb && t < (int)blockIdx.x) ? g_bsum[t] : 0;
    for (int o = 16; o; o >>= 1) v += __shfl_down_sync(0xffffffffu, v, o);
    if ((t & 31) == 0) wsum[t >> 5] = v;
    __syncthreads();
    if (t < 32) {
        int s2 = wsum[t];
        for (int o = 16; o; o >>= 1) s2 += __shfl_down_sync(0xffffffffu, s2, o);
        if (t == 0) wsum[0] = s2;
    }
    __syncthreads();
    int off = wsum[0];
    int i = blockIdx.x * SCAN_B + t;
    if (i < n) {
        g_row[i] = g_rowtmp[i] + off;
        g_dis[i] = rsqrtf((float)(g_degi[i] + 1));
    }
}

// atomic-free CSR fill using precomputed ranks
__global__ void k_csr_fill(const int* __restrict__ ei, int e_cnt) {
    int e = blockIdx.x * blockDim.x + threadIdx.x;
    if (e < e_cnt) {
        int s = ei[e];
        int d = ei[e_cnt + e];
        g_csr[g_row[d] + g_epos[e]] = s;
    }
}

// ---------------------------------------------------------------------------
// GEMM1 (fp16 mma, software-pipelined): H1h = fp16(dis .* (x @ W1^T))
// 256 threads, tile 128x128. Double-buffered x staging; W read via __ldg
// (32KB, L1-resident). Warp w: rows 32*(w>>1), cols 64*(w&1).
// ---------------------------------------------------------------------------
__global__ void __launch_bounds__(256) k_gemm1(const float* __restrict__ x, int n) {
    __shared__ unsigned xs[2][128][20];
    const unsigned* W = (const unsigned*)g_W1h4;   // [c][64] uints
    int t = threadIdx.x;
    int w = t >> 5, lane = t & 31;
    int gid = lane >> 2, tig = lane & 3;
    int rbase = (w >> 1) * 32;
    int cbase = (w & 1) * 64;
    int row0 = blockIdx.x * 128;
    int rr = t >> 3, kq = t & 7;

    float acc[2][8][4];
    #pragma unroll
    for (int m = 0; m < 2; m++)
        #pragma unroll
        for (int nt = 0; nt < 8; nt++)
            #pragma unroll
            for (int j = 0; j < 4; j++) acc[m][nt][j] = 0.0f;

    // prefetch chunk 0 (4 float4 per thread)
    float4 px[4];
    #pragma unroll
    for (int u = 0; u < 4; u++) {
        int gr = row0 + rr + 32 * u;
        px[u] = (gr < n) ? ((const float4*)x)[gr * 32 + kq]
                         : make_float4(0.f, 0.f, 0.f, 0.f);
    }

    #pragma unroll
    for (int kc = 0; kc < 4; kc++) {
        int buf = kc & 1;
        // stage current chunk (convert fp32->fp16)
        #pragma unroll
        for (int u = 0; u < 4; u++) {
            xs[buf][rr + 32 * u][kq * 2]     = pack_half2(px[u].x, px[u].y);
            xs[buf][rr + 32 * u][kq * 2 + 1] = pack_half2(px[u].z, px[u].w);
        }
        // prefetch next chunk (latency hidden behind compute below)
        if (kc < 3) {
            #pragma unroll
            for (int u = 0; u < 4; u++) {
                int gr = row0 + rr + 32 * u;
                px[u] = (gr < n) ? ((const float4*)x)[gr * 32 + (kc + 1) * 8 + kq]
                                 : make_float4(0.f, 0.f, 0.f, 0.f);
            }
        }
        __syncthreads();
        #pragma unroll
        for (int ks2 = 0; ks2 < 16; ks2 += 8) {
            unsigned a[2][4], b[8][2];
            #pragma unroll
            for (int m = 0; m < 2; m++) {
                int r0 = rbase + 16 * m + gid;
                a[m][0] = xs[buf][r0][ks2 + tig];
                a[m][1] = xs[buf][r0 + 8][ks2 + tig];
                a[m][2] = xs[buf][r0][ks2 + tig + 4];
                a[m][3] = xs[buf][r0 + 8][ks2 + tig + 4];
            }
            #pragma unroll
            for (int nt = 0; nt < 8; nt++) {
                int c = cbase + 8 * nt + gid;
                b[nt][0] = __ldg(&W[c * 64 + kc * 16 + ks2 + tig]);
                b[nt][1] = __ldg(&W[c * 64 + kc * 16 + ks2 + tig + 4]);
            }
            #pragma unroll
            for (int m = 0; m < 2; m++)
                #pragma unroll
                for (int nt = 0; nt < 8; nt++)
                    mma_f16(acc[m][nt], a[m], b[nt]);
        }
    }

    __half2* H1 = (__half2*)g_H1h;
    #pragma unroll
    for (int m = 0; m < 2; m++) {
        int r_lo = row0 + rbase + 16 * m + gid;
        int r_hi = r_lo + 8;
        float dlo = (r_lo < n) ? g_dis[r_lo] : 0.0f;
        float dhi = (r_hi < n) ? g_dis[r_hi] : 0.0f;
        #pragma unroll
        for (int nt = 0; nt < 8; nt++) {
            int c = cbase + 8 * nt + 2 * tig;
            if (r_lo < n)
                H1[r_lo * 64 + (c >> 1)] =
                    __floats2half2_rn(acc[m][nt][0] * dlo, acc[m][nt][1] * dlo);
            if (r_hi < n)
                H1[r_hi * 64 + (c >> 1)] =
                    __floats2half2_rn(acc[m][nt][2] * dhi, acc[m][nt][3] * dhi);
        }
    }
}

// ---------------------------------------------------------------------------
// layer-1 pull aggregation: half-warp (16 lanes) per node, fp16 gather,
// fp32 accumulate, fp16 store. agg[i] = dis[i]*(H1[i] + sum_s H1[s]) + b1
// ---------------------------------------------------------------------------
__global__ void __launch_bounds__(256) k_agg1(const float* __restrict__ b1, int n) {
    int t = threadIdx.x;
    int i = blockIdx.x * 16 + (t >> 4);
    int q = t & 15;
    if (i >= n) return;
    int start = g_row[i];
    int deg   = g_degi[i];
    int endj  = start + deg;
    float acc[8] = {0, 0, 0, 0, 0, 0, 0, 0};
    acc_u4(acc, g_H1h[i * 16 + q]);    // self-loop
    int j = start;
    for (; j + 3 < endj; j += 4) {
        int s0 = __ldg(&g_csr[j]),     s1 = __ldg(&g_csr[j + 1]);
        int s2 = __ldg(&g_csr[j + 2]), s3 = __ldg(&g_csr[j + 3]);
        uint4 u0 = g_H1h[s0 * 16 + q];
        uint4 u1 = g_H1h[s1 * 16 + q];
        uint4 u2 = g_H1h[s2 * 16 + q];
        uint4 u3 = g_H1h[s3 * 16 + q];
        acc_u4(acc, u0); acc_u4(acc, u1); acc_u4(acc, u2); acc_u4(acc, u3);
    }
    for (; j < endj; j++) acc_u4(acc, g_H1h[__ldg(&g_csr[j]) * 16 + q]);

    float di = g_dis[i];
    float4 b0 = ((const float4*)b1)[2 * q];
    float4 b1v = ((const float4*)b1)[2 * q + 1];
    uint4 o;
    o.x = pack_half2(fmaf(acc[0], di, b0.x),  fmaf(acc[1], di, b0.y));
    o.y = pack_half2(fmaf(acc[2], di, b0.z),  fmaf(acc[3], di, b0.w));
    o.z = pack_half2(fmaf(acc[4], di, b1v.x), fmaf(acc[5], di, b1v.y));
    o.w = pack_half2(fmaf(acc[6], di, b1v.z), fmaf(acc[7], di, b1v.w));
    g_A1h[i * 16 + q] = o;
}

// ---------------------------------------------------------------------------
// BN statistics over fp16 AGG1 (L2-resident), 4-deep MLP
// ---------------------------------------------------------------------------
__global__ void k_bnstats(int n) {
    const __half* A = (const __half*)g_A1h;
    int c = threadIdx.x;  // 128
    float s = 0.0f, s2 = 0.0f;
    int r = blockIdx.x;
    for (; r + 3 * BN_GRID < n; r += 4 * BN_GRID) {
        float v0 = __half2float(A[(r) * F1 + c]);
        float v1 = __half2float(A[(r + BN_GRID) * F1 + c]);
        float v2 = __half2float(A[(r + 2 * BN_GRID) * F1 + c]);
        float v3 = __half2float(A[(r + 3 * BN_GRID) * F1 + c]);
        s += v0 + v1 + v2 + v3;
        s2 = fmaf(v0, v0, s2); s2 = fmaf(v1, v1, s2);
        s2 = fmaf(v2, v2, s2); s2 = fmaf(v3, v3, s2);
    }
    for (; r < n; r += BN_GRID) {
        float v = __half2float(A[r * F1 + c]);
        s += v;
        s2 = fmaf(v, v, s2);
    }
    atomicAdd(&g_sums[c], s);
    atomicAdd(&g_sums[F1 + c], s2);
}

// ---------------------------------------------------------------------------
// GEMM2 (fp16 mma, software-pipelined): H2h = fp16(dis .* (relu(bn(A1h)) @ W2^T))
// BN finalize in prologue; W2 via __ldg; double-buffered A1h staging.
// ---------------------------------------------------------------------------
__global__ void __launch_bounds__(256) k_gemm2(const float* __restrict__ gamma,
                                               const float* __restrict__ beta, int n) {
    __shared__ unsigned xs[2][128][20];
    __shared__ float sc_s[F1];
    __shared__ float sh_s[F1];
    const unsigned* W = (const unsigned*)g_W2h4;   // [c][64] uints (64 rows)
    int t = threadIdx.x;
    int w = t >> 5, lane = t & 31;
    int gid = lane >> 2, tig = lane & 3;
    int rbase = w * 16;
    int row0 = blockIdx.x * 128;
    int rr = t >> 2, qq = t & 3;   // staging: rows rr, rr+64; uint4 col qq

    if (t < F1) {
        float inv_n = 1.0f / (float)n;
        float mean = g_sums[t] * inv_n;
        float var = g_sums[F1 + t] * inv_n - mean * mean;
        float inv = rsqrtf(var + BN_EPS);
        float sc = gamma[t] * inv;
        sc_s[t] = sc;
        sh_s[t] = beta[t] - mean * sc;
    }

    float acc[8][4];
    #pragma unroll
    for (int nt = 0; nt < 8; nt++)
        #pragma unroll
        for (int j = 0; j < 4; j++) acc[nt][j] = 0.0f;

    // prefetch chunk 0 (2 uint4 per thread: rows rr and rr+64)
    uint4 px[2];
    #pragma unroll
    for (int u = 0; u < 2; u++) {
        int gr = row0 + rr + 64 * u;
        px[u] = (gr < n) ? g_A1h[gr * 16 + qq]
                         : make_uint4(0u, 0u, 0u, 0u);
    }
    __syncthreads();   // sc_s/sh_s ready before staging uses them

    #pragma unroll
    for (int kc = 0; kc < 4; kc++) {
        int buf = kc & 1;
        // stage current chunk: unpack, bn+relu, repack
        #pragma unroll
        for (int u = 0; u < 2; u++) {
            int r = rr + 64 * u;
            int f = kc * 32 + 8 * qq;
            float2 f0 = __half22float2(*(__half2*)&px[u].x);
            float2 f1 = __half22float2(*(__half2*)&px[u].y);
            float2 f2 = __half22float2(*(__half2*)&px[u].z);
            float2 f3 = __half22float2(*(__half2*)&px[u].w);
            float v0 = fmaxf(fmaf(f0.x, sc_s[f + 0], sh_s[f + 0]), 0.0f);
            float v1 = fmaxf(fmaf(f0.y, sc_s[f + 1], sh_s[f + 1]), 0.0f);
            float v2 = fmaxf(fmaf(f1.x, sc_s[f + 2], sh_s[f + 2]), 0.0f);
            float v3 = fmaxf(fmaf(f1.y, sc_s[f + 3], sh_s[f + 3]), 0.0f);
            float v4 = fmaxf(fmaf(f2.x, sc_s[f + 4], sh_s[f + 4]), 0.0f);
            float v5 = fmaxf(fmaf(f2.y, sc_s[f + 5], sh_s[f + 5]), 0.0f);
            float v6 = fmaxf(fmaf(f3.x, sc_s[f + 6], sh_s[f + 6]), 0.0f);
            float v7 = fmaxf(fmaf(f3.y, sc_s[f + 7], sh_s[f + 7]), 0.0f);
            xs[buf][r][qq * 4 + 0] = pack_half2(v0, v1);
            xs[buf][r][qq * 4 + 1] = pack_half2(v2, v3);
            xs[buf][r][qq * 4 + 2] = pack_half2(v4, v5);
            xs[buf][r][qq * 4 + 3] = pack_half2(v6, v7);
        }
        // prefetch next chunk
        if (kc < 3) {
            #pragma unroll
            for (int u = 0; u < 2; u++) {
                int gr = row0 + rr + 64 * u;
                px[u] = (gr < n) ? g_A1h[gr * 16 + (kc + 1) * 4 + qq]
                                 : make_uint4(0u, 0u, 0u, 0u);
            }
        }
        __syncthreads();
        #pragma unroll
        for (int ks2 = 0; ks2 < 16; ks2 += 8) {
            unsigned a[4], b[8][2];
            {
                int r0 = rbase + gid;
                a[0] = xs[buf][r0][ks2 + tig];
                a[1] = xs[buf][r0 + 8][ks2 + tig];
                a[2] = xs[buf][r0][ks2 + tig + 4];
                a[3] = xs[buf][r0 + 8][ks2 + tig + 4];
            }
            #pragma unroll
            for (int nt = 0; nt < 8; nt++) {
                int c = 8 * nt + gid;
                b[nt][0] = __ldg(&W[c * 64 + kc * 16 + ks2 + tig]);
                b[nt][1] = __ldg(&W[c * 64 + kc * 16 + ks2 + tig + 4]);
            }
            #pragma unroll
            for (int nt = 0; nt < 8; nt++)
                mma_f16(acc[nt], a, b[nt]);
        }
    }

    __half2* H2 = (__half2*)g_H2h;
    int r_lo = row0 + rbase + gid;
    int r_hi = r_lo + 8;
    float dlo = (r_lo < n) ? g_dis[r_lo] : 0.0f;
    float dhi = (r_hi < n) ? g_dis[r_hi] : 0.0f;
    #pragma unroll
    for (int nt = 0; nt < 8; nt++) {
        int c = 8 * nt + 2 * tig;
        if (r_lo < n)
            H2[r_lo * 32 + (c >> 1)] =
                __floats2half2_rn(acc[nt][0] * dlo, acc[nt][1] * dlo);
        if (r_hi < n)
            H2[r_hi * 32 + (c >> 1)] =
                __floats2half2_rn(acc[nt][2] * dhi, acc[nt][3] * dhi);
    }
}

// ---------------------------------------------------------------------------
// layer-2 pull aggregation: quarter-warp (8 lanes) per node, fp16 gather,
// writes d_out fp32 directly. Also restores zeroed state for next replay.
// ---------------------------------------------------------------------------
__global__ void __launch_bounds__(256) k_agg2(const float* __restrict__ b2, int n,
                                              float4* __restrict__ out) {
    int t = threadIdx.x;
    if (blockIdx.x == 0 && t < 2 * F1) g_sums[t] = 0.0f;  // restore for replay
    int i = blockIdx.x * 32 + (t >> 3);
    int q = t & 7;
    if (i >= n) return;
    int start = g_row[i];
    int deg   = g_degi[i];
    if (q == 0) g_degi[i] = 0;         // restore for next replay
    int endj  = start + deg;
    float acc[8] = {0, 0, 0, 0, 0, 0, 0, 0};
    acc_u4(acc, g_H2h[i * 8 + q]);     // self-loop
    int j = start;
    for (; j + 3 < endj; j += 4) {
        int s0 = __ldg(&g_csr[j]),     s1 = __ldg(&g_csr[j + 1]);
        int s2 = __ldg(&g_csr[j + 2]), s3 = __ldg(&g_csr[j + 3]);
        uint4 u0 = g_H2h[s0 * 8 + q];
        uint4 u1 = g_H2h[s1 * 8 + q];
        uint4 u2 = g_H2h[s2 * 8 + q];
        uint4 u3 = g_H2h[s3 * 8 + q];
        acc_u4(acc, u0); acc_u4(acc, u1); acc_u4(acc, u2); acc_u4(acc, u3);
    }
    for (; j < endj; j++) acc_u4(acc, g_H2h[__ldg(&g_csr[j]) * 8 + q]);

    float di = g_dis[i];
    float4 b0 = ((const float4*)b2)[2 * q];
    float4 b1v = ((const float4*)b2)[2 * q + 1];
    out[i * 16 + 2 * q] =
        make_float4(fmaf(acc[0], di, b0.x), fmaf(acc[1], di, b0.y),
                    fmaf(acc[2], di, b0.z), fmaf(acc[3], di, b0.w));
    out[i * 16 + 2 * q + 1] =
        make_float4(fmaf(acc[4], di, b1v.x), fmaf(acc[5], di, b1v.y),
                    fmaf(acc[6], di, b1v.z), fmaf(acc[7], di, b1v.w));
}

// ---------------------------------------------------------------------------
extern "C" void kernel_launch(void* const* d_in, const int* in_sizes, int n_in,
                              void* d_out, int out_size) {
    const float* x     = (const float*)d_in[0];
    const int*   ei    = (const int*)d_in[1];
    const float* W1    = (const float*)d_in[2];
    const float* b1    = (const float*)d_in[3];
    const float* gamma = (const float*)d_in[4];
    const float* beta  = (const float*)d_in[5];
    const float* W2    = (const float*)d_in[6];
    const float* b2    = (const float*)d_in[7];

    int n = in_sizes[0] / F1;       // 100000
    int e = in_sizes[1] / 2;        // 1600000
    int nb = (n + SCAN_B - 1) / SCAN_B;

    // CSR build (g_degi/g_sums arrive zeroed: load-time init + agg2 restore)
    k_deg_count<<<(e + 255) / 256, 256>>>(ei, W1, W2, e);
    k_scan_block<<<nb, SCAN_B>>>(n);
    k_scan_fin<<<nb, SCAN_B>>>(n, nb);
    k_csr_fill<<<(e + 255) / 256, 256>>>(ei, e);

    // layer 1
    k_gemm1<<<(n + 127) / 128, 256>>>(x, n);
    k_agg1<<<(n + 15) / 16, 256>>>(b1, n);

    // BN stats
    k_bnstats<<<BN_GRID, 128>>>(n);

    // layer 2 (BN finalize folded into gemm2 prologue)
    k_gemm2<<<(n + 127) / 128, 256>>>(gamma, beta, n);
    k_agg2<<<(n + 31) / 32, 256>>>(b2, n, (float4*)d_out);
}

// round 13
// speedup vs baseline: 1.0396x; 1.0396x over previous
#include <cuda_runtime.h>
#include <cuda_fp16.h>

#define NMAX 100000
#define EMAX 1600000
#define F1 128
#define F2 64
#define BN_EPS 1e-5f
#define SCAN_B 1024
#define BN_GRID 1024

// ---- scratch (device globals; zero-initialized at load; no allocation) ----
__device__ float  g_dis[NMAX];             // rsqrt(degree)
__device__ int    g_degi[NMAX];            // in-degree (zero-restored by agg2)
__device__ int    g_row[NMAX];             // CSR row start
__device__ int    g_epos[EMAX];            // per-edge rank within destination
__device__ int    g_rowtmp[NMAX];          // block-local exclusive scan
__device__ int    g_bsum[128];             // scan block sums
__device__ int    g_csr[EMAX];             // src indices grouped by dst
__device__ uint4  g_H1h[NMAX * 16];        // fp16 dis*(x@W1^T)        [N,128]
__device__ float4 g_AGG1[NMAX * 32];       // layer-1 aggregated fp32  [N,128]
__device__ uint4  g_H2h[NMAX * 8];         // fp16 dis*(relu(bn)@W2^T) [N,64]
__device__ float  g_sums[2 * F1];          // BN sum/sumsq (zero-restored)
__device__ uint4  g_W1h4[F1 * F1 / 8];     // fp16 W1 row-major [c][k]; 16 uint4/row
__device__ uint4  g_W2h4[F1 * F2 / 8];     // fp16 W2 row-major [c][k]; 16 uint4/row

// ---- fp16 mma m16n8k16 (row.col, f32 accum) ----
__device__ __forceinline__ void mma_f16(float* d, const unsigned* a, const unsigned* b) {
    asm volatile(
        "mma.sync.aligned.m16n8k16.row.col.f32.f16.f16.f32 "
        "{%0,%1,%2,%3}, {%4,%5,%6,%7}, {%8,%9}, {%0,%1,%2,%3};"
        : "+f"(d[0]), "+f"(d[1]), "+f"(d[2]), "+f"(d[3])
        : "r"(a[0]), "r"(a[1]), "r"(a[2]), "r"(a[3]), "r"(b[0]), "r"(b[1]));
}

__device__ __forceinline__ unsigned pack_half2(float a, float b) {
    __half2 h = __floats2half2_rn(a, b);
    return *reinterpret_cast<unsigned*>(&h);
}

// fp16 row accumulate: acc[0..7] += unpack(u)
__device__ __forceinline__ void acc_u4(float* acc, uint4 u) {
    float2 f0 = __half22float2(*(__half2*)&u.x);
    float2 f1 = __half22float2(*(__half2*)&u.y);
    float2 f2 = __half22float2(*(__half2*)&u.z);
    float2 f3 = __half22float2(*(__half2*)&u.w);
    acc[0] += f0.x; acc[1] += f0.y;
    acc[2] += f1.x; acc[3] += f1.y;
    acc[4] += f2.x; acc[5] += f2.y;
    acc[6] += f3.x; acc[7] += f3.y;
}

// ---------------------------------------------------------------------------
// degree count + per-edge rank; weights -> fp16 (merged former k_init work;
// g_degi/g_sums arrive zeroed: load-time zero-init + agg2 tail-restore)
// ---------------------------------------------------------------------------
__global__ void k_deg_count(const int* __restrict__ ei,
                            const float* __restrict__ W1,
                            const float* __restrict__ W2, int e_cnt) {
    int e = blockIdx.x * blockDim.x + threadIdx.x;
    if (e < F1 * F1) ((__half*)g_W1h4)[e] = __float2half_rn(W1[e]);
    if (e < F1 * F2) ((__half*)g_W2h4)[e] = __float2half_rn(W2[e]);
    if (e < e_cnt) {
        int d = ei[e_cnt + e];
        g_epos[e] = atomicAdd(&g_degi[d], 1);
    }
}

// ---------------------------------------------------------------------------
// scan (2 stages, proven): block-exclusive -> finalize
// ---------------------------------------------------------------------------
__global__ void __launch_bounds__(SCAN_B) k_scan_block(int n) {
    __shared__ int s[SCAN_B];
    int t = threadIdx.x;
    int i = blockIdx.x * SCAN_B + t;
    int v = (i < n) ? g_degi[i] : 0;
    s[t] = v;
    __syncthreads();
    for (int off = 1; off < SCAN_B; off <<= 1) {
        int a = (t >= off) ? s[t - off] : 0;
        __syncthreads();
        s[t] += a;
        __syncthreads();
    }
    if (i < n) g_rowtmp[i] = s[t] - v;
    if (t == SCAN_B - 1) g_bsum[blockIdx.x] = s[t];
}

__global__ void __launch_bounds__(SCAN_B) k_scan_fin(int n, int nb) {
    __shared__ int wsum[32];
    int t = threadIdx.x;
    int v = (t < nb && t < (int)blockIdx.x) ? g_bsum[t] : 0;
    for (int o = 16; o; o >>= 1) v += __shfl_down_sync(0xffffffffu, v, o);
    if ((t & 31) == 0) wsum[t >> 5] = v;
    __syncthreads();
    if (t < 32) {
        int s2 = wsum[t];
        for (int o = 16; o; o >>= 1) s2 += __shfl_down_sync(0xffffffffu, s2, o);
        if (t == 0) wsum[0] = s2;
    }
    __syncthreads();
    int off = wsum[0];
    int i = blockIdx.x * SCAN_B + t;
    if (i < n) {
        g_row[i] = g_rowtmp[i] + off;
        g_dis[i] = rsqrtf((float)(g_degi[i] + 1));
    }
}

// atomic-free CSR fill using precomputed ranks
__global__ void k_csr_fill(const int* __restrict__ ei, int e_cnt) {
    int e = blockIdx.x * blockDim.x + threadIdx.x;
    if (e < e_cnt) {
        int s = ei[e];
        int d = ei[e_cnt + e];
        g_csr[g_row[d] + g_epos[e]] = s;
    }
}

// ---------------------------------------------------------------------------
// GEMM1 (fp16 mma): H1h = fp16(dis .* (x @ W1^T))   [proven R10 version]
// 256 threads, tile 128x128. Warp w: rows 32*(w>>1), cols 64*(w&1).
// ---------------------------------------------------------------------------
__global__ void __launch_bounds__(256) k_gemm1(const float* __restrict__ x, int n) {
    __shared__ unsigned xs[128][20];
    __shared__ unsigned ws[128][20];
    int t = threadIdx.x;
    int w = t >> 5, lane = t & 31;
    int gid = lane >> 2, tig = lane & 3;
    int rbase = (w >> 1) * 32;
    int cbase = (w & 1) * 64;
    int row0 = blockIdx.x * 128;

    float acc[2][8][4];
    #pragma unroll
    for (int m = 0; m < 2; m++)
        #pragma unroll
        for (int nt = 0; nt < 8; nt++)
            #pragma unroll
            for (int j = 0; j < 4; j++) acc[m][nt][j] = 0.0f;

    for (int kc = 0; kc < F1; kc += 32) {
        for (int i = t; i < 1024; i += 256) {
            int r = i >> 3, kq = i & 7;
            int gr = row0 + r;
            float4 v = make_float4(0.f, 0.f, 0.f, 0.f);
            if (gr < n) v = ((const float4*)x)[gr * 32 + (kc >> 2) + kq];
            xs[r][kq * 2]     = pack_half2(v.x, v.y);
            xs[r][kq * 2 + 1] = pack_half2(v.z, v.w);
        }
        for (int i = t; i < 512; i += 256) {
            int c = i >> 2, q = i & 3;
            *(uint4*)&ws[c][q * 4] = g_W1h4[c * 16 + (kc >> 3) + q];
        }
        __syncthreads();

        #pragma unroll
        for (int ks2 = 0; ks2 < 16; ks2 += 8) {
            unsigned a[2][4], b[8][2];
            #pragma unroll
            for (int m = 0; m < 2; m++) {
                int r0 = rbase + 16 * m + gid;
                a[m][0] = xs[r0][ks2 + tig];
                a[m][1] = xs[r0 + 8][ks2 + tig];
                a[m][2] = xs[r0][ks2 + tig + 4];
                a[m][3] = xs[r0 + 8][ks2 + tig + 4];
            }
            #pragma unroll
            for (int nt = 0; nt < 8; nt++) {
                int c = cbase + 8 * nt + gid;
                b[nt][0] = ws[c][ks2 + tig];
                b[nt][1] = ws[c][ks2 + tig + 4];
            }
            #pragma unroll
            for (int m = 0; m < 2; m++)
                #pragma unroll
                for (int nt = 0; nt < 8; nt++)
                    mma_f16(acc[m][nt], a[m], b[nt]);
        }
        __syncthreads();
    }

    __half2* H1 = (__half2*)g_H1h;
    #pragma unroll
    for (int m = 0; m < 2; m++) {
        int r_lo = row0 + rbase + 16 * m + gid;
        int r_hi = r_lo + 8;
        float dlo = (r_lo < n) ? g_dis[r_lo] : 0.0f;
        float dhi = (r_hi < n) ? g_dis[r_hi] : 0.0f;
        #pragma unroll
        for (int nt = 0; nt < 8; nt++) {
            int c = cbase + 8 * nt + 2 * tig;
            if (r_lo < n)
                H1[r_lo * 64 + (c >> 1)] =
                    __floats2half2_rn(acc[m][nt][0] * dlo, acc[m][nt][1] * dlo);
            if (r_hi < n)
                H1[r_hi * 64 + (c >> 1)] =
                    __floats2half2_rn(acc[m][nt][2] * dhi, acc[m][nt][3] * dhi);
        }
    }
}

// ---------------------------------------------------------------------------
// layer-1 pull aggregation: half-warp per node, fp16 gather, fp32 store
// agg[i] = dis[i]*(H1[i] + sum_s H1[s]) + b1     [proven R10 version]
// ---------------------------------------------------------------------------
__global__ void __launch_bounds__(256) k_agg1(const float* __restrict__ b1, int n) {
    int t = threadIdx.x;
    int i = blockIdx.x * 16 + (t >> 4);
    int q = t & 15;
    if (i >= n) return;
    int start = g_row[i];
    int deg   = g_degi[i];
    int endj  = start + deg;
    float acc[8] = {0, 0, 0, 0, 0, 0, 0, 0};
    acc_u4(acc, g_H1h[i * 16 + q]);    // self-loop
    int j = start;
    for (; j + 3 < endj; j += 4) {
        int s0 = __ldg(&g_csr[j]),     s1 = __ldg(&g_csr[j + 1]);
        int s2 = __ldg(&g_csr[j + 2]), s3 = __ldg(&g_csr[j + 3]);
        uint4 u0 = g_H1h[s0 * 16 + q];
        uint4 u1 = g_H1h[s1 * 16 + q];
        uint4 u2 = g_H1h[s2 * 16 + q];
        uint4 u3 = g_H1h[s3 * 16 + q];
        acc_u4(acc, u0); acc_u4(acc, u1); acc_u4(acc, u2); acc_u4(acc, u3);
    }
    for (; j < endj; j++) acc_u4(acc, g_H1h[__ldg(&g_csr[j]) * 16 + q]);

    float di = g_dis[i];
    float4 b0 = ((const float4*)b1)[2 * q];
    float4 b1v = ((const float4*)b1)[2 * q + 1];
    g_AGG1[i * 32 + 2 * q] =
        make_float4(fmaf(acc[0], di, b0.x), fmaf(acc[1], di, b0.y),
                    fmaf(acc[2], di, b0.z), fmaf(acc[3], di, b0.w));
    g_AGG1[i * 32 + 2 * q + 1] =
        make_float4(fmaf(acc[4], di, b1v.x), fmaf(acc[5], di, b1v.y),
                    fmaf(acc[6], di, b1v.z), fmaf(acc[7], di, b1v.w));
}

// ---------------------------------------------------------------------------
// BN statistics over AGG1 (L2-resident), 4-deep MLP   [proven R10 version]
// ---------------------------------------------------------------------------
__global__ void k_bnstats(int n) {
    const float* A = (const float*)g_AGG1;
    int c = threadIdx.x;  // 128
    float s = 0.0f, s2 = 0.0f;
    int r = blockIdx.x;
    for (; r + 3 * BN_GRID < n; r += 4 * BN_GRID) {
        float v0 = A[(r) * F1 + c];
        float v1 = A[(r + BN_GRID) * F1 + c];
        float v2 = A[(r + 2 * BN_GRID) * F1 + c];
        float v3 = A[(r + 3 * BN_GRID) * F1 + c];
        s += v0 + v1 + v2 + v3;
        s2 = fmaf(v0, v0, s2); s2 = fmaf(v1, v1, s2);
        s2 = fmaf(v2, v2, s2); s2 = fmaf(v3, v3, s2);
    }
    for (; r < n; r += BN_GRID) {
        float v = A[r * F1 + c];
        s += v;
        s2 = fmaf(v, v, s2);
    }
    atomicAdd(&g_sums[c], s);
    atomicAdd(&g_sums[F1 + c], s2);
}

// ---------------------------------------------------------------------------
// GEMM2 (fp16 mma): H2h = fp16(dis .* (relu(bn(AGG1)) @ W2^T))
// R10 version + BN finalize folded into prologue (replaces k_bnfinal).
// ---------------------------------------------------------------------------
__global__ void __launch_bounds__(256) k_gemm2(const float* __restrict__ gamma,
                                               const float* __restrict__ beta, int n) {
    __shared__ unsigned xs[128][20];
    __shared__ unsigned ws[64][20];
    __shared__ float sc_s[F1];
    __shared__ float sh_s[F1];
    const float* A = (const float*)g_AGG1;
    int t = threadIdx.x;
    int w = t >> 5, lane = t & 31;
    int gid = lane >> 2, tig = lane & 3;
    int rbase = w * 16;
    int row0 = blockIdx.x * 128;

    if (t < F1) {
        float inv_n = 1.0f / (float)n;
        float mean = g_sums[t] * inv_n;
        float var = g_sums[F1 + t] * inv_n - mean * mean;
        float inv = rsqrtf(var + BN_EPS);
        float sc = gamma[t] * inv;
        sc_s[t] = sc;
        sh_s[t] = beta[t] - mean * sc;
    }
    __syncthreads();

    float acc[8][4];
    #pragma unroll
    for (int nt = 0; nt < 8; nt++)
        #pragma unroll
        for (int j = 0; j < 4; j++) acc[nt][j] = 0.0f;

    for (int kc = 0; kc < F1; kc += 32) {
        for (int i = t; i < 1024; i += 256) {
            int r = i >> 3, kq = i & 7;
            int gr = row0 + r;
            float4 v = make_float4(0.f, 0.f, 0.f, 0.f);
            if (gr < n) {
                int f = kc + kq * 4;
                float4 a = ((const float4*)A)[gr * 32 + (kc >> 2) + kq];
                v.x = fmaxf(fmaf(a.x, sc_s[f + 0], sh_s[f + 0]), 0.0f);
                v.y = fmaxf(fmaf(a.y, sc_s[f + 1], sh_s[f + 1]), 0.0f);
                v.z = fmaxf(fmaf(a.z, sc_s[f + 2], sh_s[f + 2]), 0.0f);
                v.w = fmaxf(fmaf(a.w, sc_s[f + 3], sh_s[f + 3]), 0.0f);
            }
            xs[r][kq * 2]     = pack_half2(v.x, v.y);
            xs[r][kq * 2 + 1] = pack_half2(v.z, v.w);
        }
        if (t < 256) {
            int c = t >> 2, q = t & 3;
            *(uint4*)&ws[c][q * 4] = g_W2h4[c * 16 + (kc >> 3) + q];
        }
        __syncthreads();

        #pragma unroll
        for (int ks2 = 0; ks2 < 16; ks2 += 8) {
            unsigned a[4], b[8][2];
            {
                int r0 = rbase + gid;
                a[0] = xs[r0][ks2 + tig];
                a[1] = xs[r0 + 8][ks2 + tig];
                a[2] = xs[r0][ks2 + tig + 4];
                a[3] = xs[r0 + 8][ks2 + tig + 4];
            }
            #pragma unroll
            for (int nt = 0; nt < 8; nt++) {
                int c = 8 * nt + gid;
                b[nt][0] = ws[c][ks2 + tig];
                b[nt][1] = ws[c][ks2 + tig + 4];
            }
            #pragma unroll
            for (int nt = 0; nt < 8; nt++)
                mma_f16(acc[nt], a, b[nt]);
        }
        __syncthreads();
    }

    __half2* H2 = (__half2*)g_H2h;
    int r_lo = row0 + rbase + gid;
    int r_hi = r_lo + 8;
    float dlo = (r_lo < n) ? g_dis[r_lo] : 0.0f;
    float dhi = (r_hi < n) ? g_dis[r_hi] : 0.0f;
    #pragma unroll
    for (int nt = 0; nt < 8; nt++) {
        int c = 8 * nt + 2 * tig;
        if (r_lo < n)
            H2[r_lo * 32 + (c >> 1)] =
                __floats2half2_rn(acc[nt][0] * dlo, acc[nt][1] * dlo);
        if (r_hi < n)
            H2[r_hi * 32 + (c >> 1)] =
                __floats2half2_rn(acc[nt][2] * dhi, acc[nt][3] * dhi);
    }
}

// ---------------------------------------------------------------------------
// layer-2 pull aggregation: quarter-warp per node, fp16 gather, writes d_out.
// Restores zeroed state (g_sums, g_degi) for the next graph replay.
// ---------------------------------------------------------------------------
__global__ void __launch_bounds__(256) k_agg2(const float* __restrict__ b2, int n,
                                              float4* __restrict__ out) {
    int t = threadIdx.x;
    if (blockIdx.x == 0 && t < 2 * F1) g_sums[t] = 0.0f;  // restore for replay
    int i = blockIdx.x * 32 + (t >> 3);
    int q = t & 7;
    if (i >= n) return;
    int start = g_row[i];
    int deg   = g_degi[i];
    if (q == 0) g_degi[i] = 0;         // restore for next replay (read above)
    int endj  = start + deg;
    float acc[8] = {0, 0, 0, 0, 0, 0, 0, 0};
    acc_u4(acc, g_H2h[i * 8 + q]);     // self-loop
    int j = start;
    for (; j + 3 < endj; j += 4) {
        int s0 = __ldg(&g_csr[j]),     s1 = __ldg(&g_csr[j + 1]);
        int s2 = __ldg(&g_csr[j + 2]), s3 = __ldg(&g_csr[j + 3]);
        uint4 u0 = g_H2h[s0 * 8 + q];
        uint4 u1 = g_H2h[s1 * 8 + q];
        uint4 u2 = g_H2h[s2 * 8 + q];
        uint4 u3 = g_H2h[s3 * 8 + q];
        acc_u4(acc, u0); acc_u4(acc, u1); acc_u4(acc, u2); acc_u4(acc, u3);
    }
    for (; j < endj; j++) acc_u4(acc, g_H2h[__ldg(&g_csr[j]) * 8 + q]);

    float di = g_dis[i];
    float4 b0 = ((const float4*)b2)[2 * q];
    float4 b1v = ((const float4*)b2)[2 * q + 1];
    out[i * 16 + 2 * q] =
        make_float4(fmaf(acc[0], di, b0.x), fmaf(acc[1], di, b0.y),
                    fmaf(acc[2], di, b0.z), fmaf(acc[3], di, b0.w));
    out[i * 16 + 2 * q + 1] =
        make_float4(fmaf(acc[4], di, b1v.x), fmaf(acc[5], di, b1v.y),
                    fmaf(acc[6], di, b1v.z), fmaf(acc[7], di, b1v.w));
}

// ---------------------------------------------------------------------------
extern "C" void kernel_launch(void* const* d_in, const int* in_sizes, int n_in,
                              void* d_out, int out_size) {
    const float* x     = (const float*)d_in[0];
    const int*   ei    = (const int*)d_in[1];
    const float* W1    = (const float*)d_in[2];
    const float* b1    = (const float*)d_in[3];
    const float* gamma = (const float*)d_in[4];
    const float* beta  = (const float*)d_in[5];
    const float* W2    = (const float*)d_in[6];
    const float* b2    = (const float*)d_in[7];

    int n = in_sizes[0] / F1;       // 100000
    int e = in_sizes[1] / 2;        // 1600000
    int nb = (n + SCAN_B - 1) / SCAN_B;

    // CSR build (g_degi/g_sums arrive zeroed: load-time init + agg2 restore)
    k_deg_count<<<(e + 255) / 256, 256>>>(ei, W1, W2, e);
    k_scan_block<<<nb, SCAN_B>>>(n);
    k_scan_fin<<<nb, SCAN_B>>>(n, nb);
    k_csr_fill<<<(e + 255) / 256, 256>>>(ei, e);

    // layer 1
    k_gemm1<<<(n + 127) / 128, 256>>>(x, n);
    k_agg1<<<(n + 15) / 16, 256>>>(b1, n);

    // BN stats
    k_bnstats<<<BN_GRID, 128>>>(n);

    // layer 2 (BN finalize folded into gemm2 prologue)
    k_gemm2<<<(n + 127) / 128, 256>>>(gamma, beta, n);
    k_agg2<<<(n + 31) / 32, 256>>>(b2, n, (float4*)d_out);
}

// round 14
// speedup vs baseline: 1.1749x; 1.1302x over previous
#include <cuda_runtime.h>
#include <cuda_fp16.h>

#define NMAX 100000
#define EMAX 1600000
#define F1 128
#define F2 64
#define BN_EPS 1e-5f
#define SCAN_B 1024
#define BN_GRID 1024

// ---- scratch (device globals; zero-initialized at load; no allocation) ----
__device__ float  g_dis[NMAX];             // rsqrt(degree)
__device__ int    g_degi[NMAX];            // in-degree (zero-restored by agg2)
__device__ int    g_row[NMAX];             // CSR row start
__device__ int    g_epos[EMAX];            // per-edge rank within destination
__device__ int    g_rowtmp[NMAX];          // block-local exclusive scan
__device__ int    g_bsum[128];             // scan block sums
__device__ int    g_csr[EMAX];             // src indices grouped by dst
__device__ uint4  g_H1h[NMAX * 16];        // fp16 dis*(x@W1^T)        [N,128]
__device__ float4 g_AGG1[NMAX * 32];       // layer-1 aggregated fp32  [N,128]
__device__ uint4  g_H2h[NMAX * 8];         // fp16 dis*(relu(bn)@W2^T) [N,64]
__device__ float  g_sums[2 * F1];          // BN sum/sumsq (zero-restored)
__device__ uint4  g_W1h4[F1 * F1 / 8];     // fp16 W1 row-major [c][k]; 16 uint4/row
__device__ uint4  g_W2h4[F1 * F2 / 8];     // fp16 W2 row-major [c][k]; 16 uint4/row

// ---- fp16 mma m16n8k16 (row.col, f32 accum) ----
__device__ __forceinline__ void mma_f16(float* d, const unsigned* a, const unsigned* b) {
    asm volatile(
        "mma.sync.aligned.m16n8k16.row.col.f32.f16.f16.f32 "
        "{%0,%1,%2,%3}, {%4,%5,%6,%7}, {%8,%9}, {%0,%1,%2,%3};"
        : "+f"(d[0]), "+f"(d[1]), "+f"(d[2]), "+f"(d[3])
        : "r"(a[0]), "r"(a[1]), "r"(a[2]), "r"(a[3]), "r"(b[0]), "r"(b[1]));
}

__device__ __forceinline__ unsigned pack_half2(float a, float b) {
    __half2 h = __floats2half2_rn(a, b);
    return *reinterpret_cast<unsigned*>(&h);
}

// fp16 row accumulate: acc[0..7] += unpack(u)
__device__ __forceinline__ void acc_u4(float* acc, uint4 u) {
    float2 f0 = __half22float2(*(__half2*)&u.x);
    float2 f1 = __half22float2(*(__half2*)&u.y);
    float2 f2 = __half22float2(*(__half2*)&u.z);
    float2 f3 = __half22float2(*(__half2*)&u.w);
    acc[0] += f0.x; acc[1] += f0.y;
    acc[2] += f1.x; acc[3] += f1.y;
    acc[4] += f2.x; acc[5] += f2.y;
    acc[6] += f3.x; acc[7] += f3.y;
}

// ---------------------------------------------------------------------------
// degree count + per-edge rank; weights -> fp16
// ---------------------------------------------------------------------------
__global__ void k_deg_count(const int* __restrict__ ei,
                            const float* __restrict__ W1,
                            const float* __restrict__ W2, int e_cnt) {
    int e = blockIdx.x * blockDim.x + threadIdx.x;
    if (e < F1 * F1) ((__half*)g_W1h4)[e] = __float2half_rn(W1[e]);
    if (e < F1 * F2) ((__half*)g_W2h4)[e] = __float2half_rn(W2[e]);
    if (e < e_cnt) {
        int d = ei[e_cnt + e];
        g_epos[e] = atomicAdd(&g_degi[d], 1);
    }
}

// ---------------------------------------------------------------------------
// scan (2 stages, proven): block-exclusive -> finalize
// ---------------------------------------------------------------------------
__global__ void __launch_bounds__(SCAN_B) k_scan_block(int n) {
    __shared__ int s[SCAN_B];
    int t = threadIdx.x;
    int i = blockIdx.x * SCAN_B + t;
    int v = (i < n) ? g_degi[i] : 0;
    s[t] = v;
    __syncthreads();
    for (int off = 1; off < SCAN_B; off <<= 1) {
        int a = (t >= off) ? s[t - off] : 0;
        __syncthreads();
        s[t] += a;
        __syncthreads();
    }
    if (i < n) g_rowtmp[i] = s[t] - v;
    if (t == SCAN_B - 1) g_bsum[blockIdx.x] = s[t];
}

__global__ void __launch_bounds__(SCAN_B) k_scan_fin(int n, int nb) {
    __shared__ int wsum[32];
    int t = threadIdx.x;
    int v = (t < nb && t < (int)blockIdx.x) ? g_bsum[t] : 0;
    for (int o = 16; o; o >>= 1) v += __shfl_down_sync(0xffffffffu, v, o);
    if ((t & 31) == 0) wsum[t >> 5] = v;
    __syncthreads();
    if (t < 32) {
        int s2 = wsum[t];
        for (int o = 16; o; o >>= 1) s2 += __shfl_down_sync(0xffffffffu, s2, o);
        if (t == 0) wsum[0] = s2;
    }
    __syncthreads();
    int off = wsum[0];
    int i = blockIdx.x * SCAN_B + t;
    if (i < n) {
        g_row[i] = g_rowtmp[i] + off;
        g_dis[i] = rsqrtf((float)(g_degi[i] + 1));
    }
}

// atomic-free CSR fill using precomputed ranks
__global__ void k_csr_fill(const int* __restrict__ ei, int e_cnt) {
    int e = blockIdx.x * blockDim.x + threadIdx.x;
    if (e < e_cnt) {
        int s = ei[e];
        int d = ei[e_cnt + e];
        g_csr[g_row[d] + g_epos[e]] = s;
    }
}

// ---------------------------------------------------------------------------
// GEMM1 (fp16 mma, pipelined): H1h = fp16(dis .* (x @ W1^T))
// Full W1 staged to smem ONCE (stride 68 uints -> conflict-free b frags);
// x double-buffered with register prefetch to hide DRAM latency.
// 256 threads, tile 128x128. Warp w: rows 32*(w>>1), cols 64*(w&1).
// ---------------------------------------------------------------------------
__global__ void __launch_bounds__(256) k_gemm1(const float* __restrict__ x, int n) {
    __shared__ unsigned xs[2][128][20];
    __shared__ unsigned ws[128][68];     // full 128 cols x 64 uints (+4 pad)
    int t = threadIdx.x;
    int w = t >> 5, lane = t & 31;
    int gid = lane >> 2, tig = lane & 3;
    int rbase = (w >> 1) * 32;
    int cbase = (w & 1) * 64;
    int row0 = blockIdx.x * 128;
    int rr = t >> 3, kq = t & 7;         // x staging: rows rr+32u, float4 col kq

    // stage the ENTIRE W1 tile once (2048 uint4 / 256 threads)
    #pragma unroll
    for (int i = t; i < 2048; i += 256) {
        int c = i >> 4, q = i & 15;
        *(uint4*)&ws[c][q * 4] = g_W1h4[c * 16 + q];
    }

    float acc[2][8][4];
    #pragma unroll
    for (int m = 0; m < 2; m++)
        #pragma unroll
        for (int nt = 0; nt < 8; nt++)
            #pragma unroll
            for (int j = 0; j < 4; j++) acc[m][nt][j] = 0.0f;

    // prefetch x chunk 0 (4 float4 per thread)
    float4 px[4];
    #pragma unroll
    for (int u = 0; u < 4; u++) {
        int gr = row0 + rr + 32 * u;
        px[u] = (gr < n) ? ((const float4*)x)[gr * 32 + kq]
                         : make_float4(0.f, 0.f, 0.f, 0.f);
    }

    #pragma unroll
    for (int kc = 0; kc < 4; kc++) {
        int buf = kc & 1;
        // stage current chunk (fp32 -> fp16)
        #pragma unroll
        for (int u = 0; u < 4; u++) {
            xs[buf][rr + 32 * u][kq * 2]     = pack_half2(px[u].x, px[u].y);
            xs[buf][rr + 32 * u][kq * 2 + 1] = pack_half2(px[u].z, px[u].w);
        }
        // prefetch next chunk (latency hidden behind MMA below)
        if (kc < 3) {
            #pragma unroll
            for (int u = 0; u < 4; u++) {
                int gr = row0 + rr + 32 * u;
                px[u] = (gr < n) ? ((const float4*)x)[gr * 32 + (kc + 1) * 8 + kq]
                                 : make_float4(0.f, 0.f, 0.f, 0.f);
            }
        }
        __syncthreads();   // also covers W staging before first MMA

        #pragma unroll
        for (int ks2 = 0; ks2 < 16; ks2 += 8) {
            unsigned a[2][4], b[8][2];
            #pragma unroll
            for (int m = 0; m < 2; m++) {
                int r0 = rbase + 16 * m + gid;
                a[m][0] = xs[buf][r0][ks2 + tig];
                a[m][1] = xs[buf][r0 + 8][ks2 + tig];
                a[m][2] = xs[buf][r0][ks2 + tig + 4];
                a[m][3] = xs[buf][r0 + 8][ks2 + tig + 4];
            }
            #pragma unroll
            for (int nt = 0; nt < 8; nt++) {
                int c = cbase + 8 * nt + gid;
                b[nt][0] = ws[c][kc * 16 + ks2 + tig];
                b[nt][1] = ws[c][kc * 16 + ks2 + tig + 4];
            }
            #pragma unroll
            for (int m = 0; m < 2; m++)
                #pragma unroll
                for (int nt = 0; nt < 8; nt++)
                    mma_f16(acc[m][nt], a[m], b[nt]);
        }
    }

    __half2* H1 = (__half2*)g_H1h;
    #pragma unroll
    for (int m = 0; m < 2; m++) {
        int r_lo = row0 + rbase + 16 * m + gid;
        int r_hi = r_lo + 8;
        float dlo = (r_lo < n) ? g_dis[r_lo] : 0.0f;
        float dhi = (r_hi < n) ? g_dis[r_hi] : 0.0f;
        #pragma unroll
        for (int nt = 0; nt < 8; nt++) {
            int c = cbase + 8 * nt + 2 * tig;
            if (r_lo < n)
                H1[r_lo * 64 + (c >> 1)] =
                    __floats2half2_rn(acc[m][nt][0] * dlo, acc[m][nt][1] * dlo);
            if (r_hi < n)
                H1[r_hi * 64 + (c >> 1)] =
                    __floats2half2_rn(acc[m][nt][2] * dhi, acc[m][nt][3] * dhi);
        }
    }
}

// ---------------------------------------------------------------------------
// layer-1 pull aggregation: half-warp per node, fp16 gather, fp32 store
// agg[i] = dis[i]*(H1[i] + sum_s H1[s]) + b1     [proven version]
// ---------------------------------------------------------------------------
__global__ void __launch_bounds__(256) k_agg1(const float* __restrict__ b1, int n) {
    int t = threadIdx.x;
    int i = blockIdx.x * 16 + (t >> 4);
    int q = t & 15;
    if (i >= n) return;
    int start = g_row[i];
    int deg   = g_degi[i];
    int endj  = start + deg;
    float acc[8] = {0, 0, 0, 0, 0, 0, 0, 0};
    acc_u4(acc, g_H1h[i * 16 + q]);    // self-loop
    int j = start;
    for (; j + 3 < endj; j += 4) {
        int s0 = __ldg(&g_csr[j]),     s1 = __ldg(&g_csr[j + 1]);
        int s2 = __ldg(&g_csr[j + 2]), s3 = __ldg(&g_csr[j + 3]);
        uint4 u0 = g_H1h[s0 * 16 + q];
        uint4 u1 = g_H1h[s1 * 16 + q];
        uint4 u2 = g_H1h[s2 * 16 + q];
        uint4 u3 = g_H1h[s3 * 16 + q];
        acc_u4(acc, u0); acc_u4(acc, u1); acc_u4(acc, u2); acc_u4(acc, u3);
    }
    for (; j < endj; j++) acc_u4(acc, g_H1h[__ldg(&g_csr[j]) * 16 + q]);

    float di = g_dis[i];
    float4 b0 = ((const float4*)b1)[2 * q];
    float4 b1v = ((const float4*)b1)[2 * q + 1];
    g_AGG1[i * 32 + 2 * q] =
        make_float4(fmaf(acc[0], di, b0.x), fmaf(acc[1], di, b0.y),
                    fmaf(acc[2], di, b0.z), fmaf(acc[3], di, b0.w));
    g_AGG1[i * 32 + 2 * q + 1] =
        make_float4(fmaf(acc[4], di, b1v.x), fmaf(acc[5], di, b1v.y),
                    fmaf(acc[6], di, b1v.z), fmaf(acc[7], di, b1v.w));
}

// ---------------------------------------------------------------------------
// BN statistics over AGG1 (L2-resident), 4-deep MLP
// ---------------------------------------------------------------------------
__global__ void k_bnstats(int n) {
    const float* A = (const float*)g_AGG1;
    int c = threadIdx.x;  // 128
    float s = 0.0f, s2 = 0.0f;
    int r = blockIdx.x;
    for (; r + 3 * BN_GRID < n; r += 4 * BN_GRID) {
        float v0 = A[(r) * F1 + c];
        float v1 = A[(r + BN_GRID) * F1 + c];
        float v2 = A[(r + 2 * BN_GRID) * F1 + c];
        float v3 = A[(r + 3 * BN_GRID) * F1 + c];
        s += v0 + v1 + v2 + v3;
        s2 = fmaf(v0, v0, s2); s2 = fmaf(v1, v1, s2);
        s2 = fmaf(v2, v2, s2); s2 = fmaf(v3, v3, s2);
    }
    for (; r < n; r += BN_GRID) {
        float v = A[r * F1 + c];
        s += v;
        s2 = fmaf(v, v, s2);
    }
    atomicAdd(&g_sums[c], s);
    atomicAdd(&g_sums[F1 + c], s2);
}

// ---------------------------------------------------------------------------
// GEMM2 (fp16 mma, pipelined): H2h = fp16(dis .* (relu(bn(AGG1)) @ W2^T))
// Full W2 staged once; A double-buffered with register prefetch; BN+ReLU
// applied at staging; BN finalize in prologue.
// ---------------------------------------------------------------------------
__global__ void __launch_bounds__(256) k_gemm2(const float* __restrict__ gamma,
                                               const float* __restrict__ beta, int n) {
    __shared__ unsigned xs[2][128][20];
    __shared__ unsigned ws[64][68];      // full 64 cols x 64 uints (+4 pad)
    __shared__ float sc_s[F1];
    __shared__ float sh_s[F1];
    const float* A = (const float*)g_AGG1;
    int t = threadIdx.x;
    int w = t >> 5, lane = t & 31;
    int gid = lane >> 2, tig = lane & 3;
    int rbase = w * 16;
    int row0 = blockIdx.x * 128;
    int rr = t >> 3, kq = t & 7;

    // stage the ENTIRE W2 tile once (1024 uint4 / 256 threads)
    #pragma unroll
    for (int i = t; i < 1024; i += 256) {
        int c = i >> 4, q = i & 15;
        *(uint4*)&ws[c][q * 4] = g_W2h4[c * 16 + q];
    }
    if (t < F1) {
        float inv_n = 1.0f / (float)n;
        float mean = g_sums[t] * inv_n;
        float var = g_sums[F1 + t] * inv_n - mean * mean;
        float inv = rsqrtf(var + BN_EPS);
        float sc = gamma[t] * inv;
        sc_s[t] = sc;
        sh_s[t] = beta[t] - mean * sc;
    }

    float acc[8][4];
    #pragma unroll
    for (int nt = 0; nt < 8; nt++)
        #pragma unroll
        for (int j = 0; j < 4; j++) acc[nt][j] = 0.0f;

    // prefetch A chunk 0 (4 float4 per thread)
    float4 px[4];
    #pragma unroll
    for (int u = 0; u < 4; u++) {
        int gr = row0 + rr + 32 * u;
        px[u] = (gr < n) ? ((const float4*)A)[gr * 32 + kq]
                         : make_float4(0.f, 0.f, 0.f, 0.f);
    }
    __syncthreads();   // sc_s/sh_s (and ws) ready before staging / MMA

    #pragma unroll
    for (int kc = 0; kc < 4; kc++) {
        int buf = kc & 1;
        // stage current chunk: bn + relu + fp16 pack
        #pragma unroll
        for (int u = 0; u < 4; u++) {
            int f = kc * 32 + kq * 4;
            float v0 = fmaxf(fmaf(px[u].x, sc_s[f + 0], sh_s[f + 0]), 0.0f);
            float v1 = fmaxf(fmaf(px[u].y, sc_s[f + 1], sh_s[f + 1]), 0.0f);
            float v2 = fmaxf(fmaf(px[u].z, sc_s[f + 2], sh_s[f + 2]), 0.0f);
            float v3 = fmaxf(fmaf(px[u].w, sc_s[f + 3], sh_s[f + 3]), 0.0f);
            xs[buf][rr + 32 * u][kq * 2]     = pack_half2(v0, v1);
            xs[buf][rr + 32 * u][kq * 2 + 1] = pack_half2(v2, v3);
        }
        // prefetch next chunk
        if (kc < 3) {
            #pragma unroll
            for (int u = 0; u < 4; u++) {
                int gr = row0 + rr + 32 * u;
                px[u] = (gr < n) ? ((const float4*)A)[gr * 32 + (kc + 1) * 8 + kq]
                                 : make_float4(0.f, 0.f, 0.f, 0.f);
            }
        }
        __syncthreads();

        #pragma unroll
        for (int ks2 = 0; ks2 < 16; ks2 += 8) {
            unsigned a[4], b[8][2];
            {
                int r0 = rbase + gid;
                a[0] = xs[buf][r0][ks2 + tig];
                a[1] = xs[buf][r0 + 8][ks2 + tig];
                a[2] = xs[buf][r0][ks2 + tig + 4];
                a[3] = xs[buf][r0 + 8][ks2 + tig + 4];
            }
            #pragma unroll
            for (int nt = 0; nt < 8; nt++) {
                int c = 8 * nt + gid;
                b[nt][0] = ws[c][kc * 16 + ks2 + tig];
                b[nt][1] = ws[c][kc * 16 + ks2 + tig + 4];
            }
            #pragma unroll
            for (int nt = 0; nt < 8; nt++)
                mma_f16(acc[nt], a, b[nt]);
        }
    }

    __half2* H2 = (__half2*)g_H2h;
    int r_lo = row0 + rbase + gid;
    int r_hi = r_lo + 8;
    float dlo = (r_lo < n) ? g_dis[r_lo] : 0.0f;
    float dhi = (r_hi < n) ? g_dis[r_hi] : 0.0f;
    #pragma unroll
    for (int nt = 0; nt < 8; nt++) {
        int c = 8 * nt + 2 * tig;
        if (r_lo < n)
            H2[r_lo * 32 + (c >> 1)] =
                __floats2half2_rn(acc[nt][0] * dlo, acc[nt][1] * dlo);
        if (r_hi < n)
            H2[r_hi * 32 + (c >> 1)] =
                __floats2half2_rn(acc[nt][2] * dhi, acc[nt][3] * dhi);
    }
}

// ---------------------------------------------------------------------------
// layer-2 pull aggregation: quarter-warp per node, fp16 gather, writes d_out.
// Restores zeroed state (g_sums, g_degi) for the next graph replay.
// ---------------------------------------------------------------------------
__global__ void __launch_bounds__(256) k_agg2(const float* __restrict__ b2, int n,
                                              float4* __restrict__ out) {
    int t = threadIdx.x;
    if (blockIdx.x == 0 && t < 2 * F1) g_sums[t] = 0.0f;  // restore for replay
    int i = blockIdx.x * 32 + (t >> 3);
    int q = t & 7;
    if (i >= n) return;
    int start = g_row[i];
    int deg   = g_degi[i];
    if (q == 0) g_degi[i] = 0;         // restore for next replay (read above)
    int endj  = start + deg;
    float acc[8] = {0, 0, 0, 0, 0, 0, 0, 0};
    acc_u4(acc, g_H2h[i * 8 + q]);     // self-loop
    int j = start;
    for (; j + 3 < endj; j += 4) {
        int s0 = __ldg(&g_csr[j]),     s1 = __ldg(&g_csr[j + 1]);
        int s2 = __ldg(&g_csr[j + 2]), s3 = __ldg(&g_csr[j + 3]);
        uint4 u0 = g_H2h[s0 * 8 + q];
        uint4 u1 = g_H2h[s1 * 8 + q];
        uint4 u2 = g_H2h[s2 * 8 + q];
        uint4 u3 = g_H2h[s3 * 8 + q];
        acc_u4(acc, u0); acc_u4(acc, u1); acc_u4(acc, u2); acc_u4(acc, u3);
    }
    for (; j < endj; j++) acc_u4(acc, g_H2h[__ldg(&g_csr[j]) * 8 + q]);

    float di = g_dis[i];
    float4 b0 = ((const float4*)b2)[2 * q];
    float4 b1v = ((const float4*)b2)[2 * q + 1];
    out[i * 16 + 2 * q] =
        make_float4(fmaf(acc[0], di, b0.x), fmaf(acc[1], di, b0.y),
                    fmaf(acc[2], di, b0.z), fmaf(acc[3], di, b0.w));
    out[i * 16 + 2 * q + 1] =
        make_float4(fmaf(acc[4], di, b1v.x), fmaf(acc[5], di, b1v.y),
                    fmaf(acc[6], di, b1v.z), fmaf(acc[7], di, b1v.w));
}

// ---------------------------------------------------------------------------
extern "C" void kernel_launch(void* const* d_in, const int* in_sizes, int n_in,
                              void* d_out, int out_size) {
    const float* x     = (const float*)d_in[0];
    const int*   ei    = (const int*)d_in[1];
    const float* W1    = (const float*)d_in[2];
    const float* b1    = (const float*)d_in[3];
    const float* gamma = (const float*)d_in[4];
    const float* beta  = (const float*)d_in[5];
    const float* W2    = (const float*)d_in[6];
    const float* b2    = (const float*)d_in[7];

    int n = in_sizes[0] / F1;       // 100000
    int e = in_sizes[1] / 2;        // 1600000
    int nb = (n + SCAN_B - 1) / SCAN_B;

    // CSR build (g_degi/g_sums arrive zeroed: load-time init + agg2 restore)
    k_deg_count<<<(e + 255) / 256, 256>>>(ei, W1, W2, e);
    k_scan_block<<<nb, SCAN_B>>>(n);
    k_scan_fin<<<nb, SCAN_B>>>(n, nb);
    k_csr_fill<<<(e + 255) / 256, 256>>>(ei, e);

    // layer 1
    k_gemm1<<<(n + 127) / 128, 256>>>(x, n);
    k_agg1<<<(n + 15) / 16, 256>>>(b1, n);

    // BN stats
    k_bnstats<<<BN_GRID, 128>>>(n);

    // layer 2 (BN finalize folded into gemm2 prologue)
    k_gemm2<<<(n + 127) / 128, 256>>>(gamma, beta, n);
    k_agg2<<<(n + 31) / 32, 256>>>(b2, n, (float4*)d_out);
}

// round 15
// speedup vs baseline: 1.2080x; 1.0282x over previous
#include <cuda_runtime.h>
#include <cuda_fp16.h>

#define NMAX 100000
#define EMAX 1600000
#define F1 128
#define F2 64
#define BN_EPS 1e-5f
#define SCAN_B 1024
#define BN_GRID 1024

// ---- scratch (device globals; zero-initialized at load; no allocation) ----
__device__ float  g_dis[NMAX];             // rsqrt(degree)
__device__ int    g_degi[NMAX];            // in-degree (zero-restored by agg2)
__device__ int    g_row[NMAX];             // CSR row start
__device__ int    g_epos[EMAX];            // per-edge rank within destination
__device__ int    g_rowtmp[NMAX];          // block-local exclusive scan
__device__ int    g_bsum[128];             // scan block sums
__device__ int    g_csr[EMAX];             // src indices grouped by dst
__device__ uint4  g_H1h[NMAX * 16];        // fp16 (x@W1^T) UNSCALED   [N,128]
__device__ float4 g_AGG1[NMAX * 32];       // layer-1 aggregated fp32  [N,128]
__device__ uint4  g_H2h[NMAX * 8];         // fp16 dis*(relu(bn)@W2^T) [N,64]
__device__ float  g_sums[2 * F1];          // BN sum/sumsq (zero-restored)
__device__ uint4  g_W2h4[F1 * F2 / 8];     // fp16 W2 row-major [c][k]; 16 uint4/row

// ---- fp16 mma m16n8k16 (row.col, f32 accum) ----
__device__ __forceinline__ void mma_f16(float* d, const unsigned* a, const unsigned* b) {
    asm volatile(
        "mma.sync.aligned.m16n8k16.row.col.f32.f16.f16.f32 "
        "{%0,%1,%2,%3}, {%4,%5,%6,%7}, {%8,%9}, {%0,%1,%2,%3};"
        : "+f"(d[0]), "+f"(d[1]), "+f"(d[2]), "+f"(d[3])
        : "r"(a[0]), "r"(a[1]), "r"(a[2]), "r"(a[3]), "r"(b[0]), "r"(b[1]));
}

__device__ __forceinline__ unsigned pack_half2(float a, float b) {
    __half2 h = __floats2half2_rn(a, b);
    return *reinterpret_cast<unsigned*>(&h);
}

// fp16 row accumulate: acc[0..7] += unpack(u)
__device__ __forceinline__ void acc_u4(float* acc, uint4 u) {
    float2 f0 = __half22float2(*(__half2*)&u.x);
    float2 f1 = __half22float2(*(__half2*)&u.y);
    float2 f2 = __half22float2(*(__half2*)&u.z);
    float2 f3 = __half22float2(*(__half2*)&u.w);
    acc[0] += f0.x; acc[1] += f0.y;
    acc[2] += f1.x; acc[3] += f1.y;
    acc[4] += f2.x; acc[5] += f2.y;
    acc[6] += f3.x; acc[7] += f3.y;
}

// fp16 row fma: acc[0..7] += s * unpack(u)
__device__ __forceinline__ void fma_u4(float* acc, uint4 u, float s) {
    float2 f0 = __half22float2(*(__half2*)&u.x);
    float2 f1 = __half22float2(*(__half2*)&u.y);
    float2 f2 = __half22float2(*(__half2*)&u.z);
    float2 f3 = __half22float2(*(__half2*)&u.w);
    acc[0] = fmaf(f0.x, s, acc[0]); acc[1] = fmaf(f0.y, s, acc[1]);
    acc[2] = fmaf(f1.x, s, acc[2]); acc[3] = fmaf(f1.y, s, acc[3]);
    acc[4] = fmaf(f2.x, s, acc[4]); acc[5] = fmaf(f2.y, s, acc[5]);
    acc[6] = fmaf(f3.x, s, acc[6]); acc[7] = fmaf(f3.y, s, acc[7]);
}

// ---------------------------------------------------------------------------
// degree count + per-edge rank; W2 -> fp16 (W1 handled inside gemm1)
// ---------------------------------------------------------------------------
__global__ void k_deg_count(const int* __restrict__ ei,
                            const float* __restrict__ W2, int e_cnt) {
    int e = blockIdx.x * blockDim.x + threadIdx.x;
    if (e < F1 * F2) ((__half*)g_W2h4)[e] = __float2half_rn(W2[e]);
    if (e < e_cnt) {
        int d = ei[e_cnt + e];
        g_epos[e] = atomicAdd(&g_degi[d], 1);
    }
}

// ---------------------------------------------------------------------------
// scan (2 stages, proven): block-exclusive -> finalize
// ---------------------------------------------------------------------------
__global__ void __launch_bounds__(SCAN_B) k_scan_block(int n) {
    __shared__ int s[SCAN_B];
    int t = threadIdx.x;
    int i = blockIdx.x * SCAN_B + t;
    int v = (i < n) ? g_degi[i] : 0;
    s[t] = v;
    __syncthreads();
    for (int off = 1; off < SCAN_B; off <<= 1) {
        int a = (t >= off) ? s[t - off] : 0;
        __syncthreads();
        s[t] += a;
        __syncthreads();
    }
    if (i < n) g_rowtmp[i] = s[t] - v;
    if (t == SCAN_B - 1) g_bsum[blockIdx.x] = s[t];
}

__global__ void __launch_bounds__(SCAN_B) k_scan_fin(int n, int nb) {
    __shared__ int wsum[32];
    int t = threadIdx.x;
    int v = (t < nb && t < (int)blockIdx.x) ? g_bsum[t] : 0;
    for (int o = 16; o; o >>= 1) v += __shfl_down_sync(0xffffffffu, v, o);
    if ((t & 31) == 0) wsum[t >> 5] = v;
    __syncthreads();
    if (t < 32) {
        int s2 = wsum[t];
        for (int o = 16; o; o >>= 1) s2 += __shfl_down_sync(0xffffffffu, s2, o);
        if (t == 0) wsum[0] = s2;
    }
    __syncthreads();
    int off = wsum[0];
    int i = blockIdx.x * SCAN_B + t;
    if (i < n) {
        g_row[i] = g_rowtmp[i] + off;
        g_dis[i] = rsqrtf((float)(g_degi[i] + 1));
    }
}

// atomic-free CSR fill using precomputed ranks
__global__ void k_csr_fill(const int* __restrict__ ei, int e_cnt) {
    int e = blockIdx.x * blockDim.x + threadIdx.x;
    if (e < e_cnt) {
        int s = ei[e];
        int d = ei[e_cnt + e];
        g_csr[g_row[d] + g_epos[e]] = s;
    }
}

// ---------------------------------------------------------------------------
// GEMM1 (fp16 mma, pipelined, CSR-independent): H1h = fp16(x @ W1^T)
// W1 converted fp32->fp16 at staging (no g_dis, no precomputed W1h).
// Full W1 staged once (stride 68); x double-buffered w/ register prefetch.
// ---------------------------------------------------------------------------
__global__ void __launch_bounds__(256) k_gemm1(const float* __restrict__ x,
                                               const float* __restrict__ W1, int n) {
    __shared__ unsigned xs[2][128][20];
    __shared__ unsigned ws[128][68];     // full 128 cols x 64 uints (+4 pad)
    int t = threadIdx.x;
    int w = t >> 5, lane = t & 31;
    int gid = lane >> 2, tig = lane & 3;
    int rbase = (w >> 1) * 32;
    int cbase = (w & 1) * 64;
    int row0 = blockIdx.x * 128;
    int rr = t >> 3, kq = t & 7;

    // stage the ENTIRE W1 tile once, converting fp32 -> fp16
    #pragma unroll
    for (int i = t; i < 4096; i += 256) {       // 4096 float4 = 128x128 fp32
        int c = i >> 5, kf = i & 31;            // row c, float4 index kf
        float4 v = ((const float4*)W1)[c * 32 + kf];
        ws[c][kf * 2]     = pack_half2(v.x, v.y);
        ws[c][kf * 2 + 1] = pack_half2(v.z, v.w);
    }

    float acc[2][8][4];
    #pragma unroll
    for (int m = 0; m < 2; m++)
        #pragma unroll
        for (int nt = 0; nt < 8; nt++)
            #pragma unroll
            for (int j = 0; j < 4; j++) acc[m][nt][j] = 0.0f;

    // prefetch x chunk 0
    float4 px[4];
    #pragma unroll
    for (int u = 0; u < 4; u++) {
        int gr = row0 + rr + 32 * u;
        px[u] = (gr < n) ? ((const float4*)x)[gr * 32 + kq]
                         : make_float4(0.f, 0.f, 0.f, 0.f);
    }

    #pragma unroll
    for (int kc = 0; kc < 4; kc++) {
        int buf = kc & 1;
        #pragma unroll
        for (int u = 0; u < 4; u++) {
            xs[buf][rr + 32 * u][kq * 2]     = pack_half2(px[u].x, px[u].y);
            xs[buf][rr + 32 * u][kq * 2 + 1] = pack_half2(px[u].z, px[u].w);
        }
        if (kc < 3) {
            #pragma unroll
            for (int u = 0; u < 4; u++) {
                int gr = row0 + rr + 32 * u;
                px[u] = (gr < n) ? ((const float4*)x)[gr * 32 + (kc + 1) * 8 + kq]
                                 : make_float4(0.f, 0.f, 0.f, 0.f);
            }
        }
        __syncthreads();   // also covers W staging before first MMA

        #pragma unroll
        for (int ks2 = 0; ks2 < 16; ks2 += 8) {
            unsigned a[2][4], b[8][2];
            #pragma unroll
            for (int m = 0; m < 2; m++) {
                int r0 = rbase + 16 * m + gid;
                a[m][0] = xs[buf][r0][ks2 + tig];
                a[m][1] = xs[buf][r0 + 8][ks2 + tig];
                a[m][2] = xs[buf][r0][ks2 + tig + 4];
                a[m][3] = xs[buf][r0 + 8][ks2 + tig + 4];
            }
            #pragma unroll
            for (int nt = 0; nt < 8; nt++) {
                int c = cbase + 8 * nt + gid;
                b[nt][0] = ws[c][kc * 16 + ks2 + tig];
                b[nt][1] = ws[c][kc * 16 + ks2 + tig + 4];
            }
            #pragma unroll
            for (int m = 0; m < 2; m++)
                #pragma unroll
                for (int nt = 0; nt < 8; nt++)
                    mma_f16(acc[m][nt], a[m], b[nt]);
        }
    }

    // epilogue: store UNSCALED fp16 (dis applied in agg1)
    __half2* H1 = (__half2*)g_H1h;
    #pragma unroll
    for (int m = 0; m < 2; m++) {
        int r_lo = row0 + rbase + 16 * m + gid;
        int r_hi = r_lo + 8;
        #pragma unroll
        for (int nt = 0; nt < 8; nt++) {
            int c = cbase + 8 * nt + 2 * tig;
            if (r_lo < n)
                H1[r_lo * 64 + (c >> 1)] =
                    __floats2half2_rn(acc[m][nt][0], acc[m][nt][1]);
            if (r_hi < n)
                H1[r_hi * 64 + (c >> 1)] =
                    __floats2half2_rn(acc[m][nt][2], acc[m][nt][3]);
        }
    }
}

// ---------------------------------------------------------------------------
// layer-1 pull aggregation: half-warp per node, fp16 gather with per-edge
// dis[s] scaling. agg[i] = dis[i]*(dis[i]*H1[i] + sum_s dis[s]*H1[s]) + b1
// ---------------------------------------------------------------------------
__global__ void __launch_bounds__(256) k_agg1(const float* __restrict__ b1, int n) {
    int t = threadIdx.x;
    int i = blockIdx.x * 16 + (t >> 4);
    int q = t & 15;
    if (i >= n) return;
    int start = g_row[i];
    int deg   = g_degi[i];
    int endj  = start + deg;
    float di = g_dis[i];
    float acc[8] = {0, 0, 0, 0, 0, 0, 0, 0};
    fma_u4(acc, g_H1h[i * 16 + q], di);          // self-loop: dis[i]*H1[i]
    int j = start;
    for (; j + 3 < endj; j += 4) {
        int s0 = __ldg(&g_csr[j]),     s1 = __ldg(&g_csr[j + 1]);
        int s2 = __ldg(&g_csr[j + 2]), s3 = __ldg(&g_csr[j + 3]);
        float d0 = __ldg(&g_dis[s0]), d1 = __ldg(&g_dis[s1]);
        float d2 = __ldg(&g_dis[s2]), d3 = __ldg(&g_dis[s3]);
        uint4 u0 = g_H1h[s0 * 16 + q];
        uint4 u1 = g_H1h[s1 * 16 + q];
        uint4 u2 = g_H1h[s2 * 16 + q];
        uint4 u3 = g_H1h[s3 * 16 + q];
        fma_u4(acc, u0, d0); fma_u4(acc, u1, d1);
        fma_u4(acc, u2, d2); fma_u4(acc, u3, d3);
    }
    for (; j < endj; j++) {
        int s = __ldg(&g_csr[j]);
        fma_u4(acc, g_H1h[s * 16 + q], __ldg(&g_dis[s]));
    }

    float4 b0 = ((const float4*)b1)[2 * q];
    float4 b1v = ((const float4*)b1)[2 * q + 1];
    g_AGG1[i * 32 + 2 * q] =
        make_float4(fmaf(acc[0], di, b0.x), fmaf(acc[1], di, b0.y),
                    fmaf(acc[2], di, b0.z), fmaf(acc[3], di, b0.w));
    g_AGG1[i * 32 + 2 * q + 1] =
        make_float4(fmaf(acc[4], di, b1v.x), fmaf(acc[5], di, b1v.y),
                    fmaf(acc[6], di, b1v.z), fmaf(acc[7], di, b1v.w));
}

// ---------------------------------------------------------------------------
// BN statistics over AGG1 (L2-resident), 4-deep MLP
// ---------------------------------------------------------------------------
__global__ void k_bnstats(int n) {
    const float* A = (const float*)g_AGG1;
    int c = threadIdx.x;  // 128
    float s = 0.0f, s2 = 0.0f;
    int r = blockIdx.x;
    for (; r + 3 * BN_GRID < n; r += 4 * BN_GRID) {
        float v0 = A[(r) * F1 + c];
        float v1 = A[(r + BN_GRID) * F1 + c];
        float v2 = A[(r + 2 * BN_GRID) * F1 + c];
        float v3 = A[(r + 3 * BN_GRID) * F1 + c];
        s += v0 + v1 + v2 + v3;
        s2 = fmaf(v0, v0, s2); s2 = fmaf(v1, v1, s2);
        s2 = fmaf(v2, v2, s2); s2 = fmaf(v3, v3, s2);
    }
    for (; r < n; r += BN_GRID) {
        float v = A[r * F1 + c];
        s += v;
        s2 = fmaf(v, v, s2);
    }
    atomicAdd(&g_sums[c], s);
    atomicAdd(&g_sums[F1 + c], s2);
}

// ---------------------------------------------------------------------------
// GEMM2 (fp16 mma, pipelined): H2h = fp16(dis .* (relu(bn(AGG1)) @ W2^T))
// Full W2 staged once; A double-buffered; BN+ReLU at staging; BN finalize
// in prologue.
// ---------------------------------------------------------------------------
__global__ void __launch_bounds__(256) k_gemm2(const float* __restrict__ gamma,
                                               const float* __restrict__ beta, int n) {
    __shared__ unsigned xs[2][128][20];
    __shared__ unsigned ws[64][68];
    __shared__ float sc_s[F1];
    __shared__ float sh_s[F1];
    const float* A = (const float*)g_AGG1;
    int t = threadIdx.x;
    int w = t >> 5, lane = t & 31;
    int gid = lane >> 2, tig = lane & 3;
    int rbase = w * 16;
    int row0 = blockIdx.x * 128;
    int rr = t >> 3, kq = t & 7;

    #pragma unroll
    for (int i = t; i < 1024; i += 256) {
        int c = i >> 4, q = i & 15;
        *(uint4*)&ws[c][q * 4] = g_W2h4[c * 16 + q];
    }
    if (t < F1) {
        float inv_n = 1.0f / (float)n;
        float mean = g_sums[t] * inv_n;
        float var = g_sums[F1 + t] * inv_n - mean * mean;
        float inv = rsqrtf(var + BN_EPS);
        float sc = gamma[t] * inv;
        sc_s[t] = sc;
        sh_s[t] = beta[t] - mean * sc;
    }

    float acc[8][4];
    #pragma unroll
    for (int nt = 0; nt < 8; nt++)
        #pragma unroll
        for (int j = 0; j < 4; j++) acc[nt][j] = 0.0f;

    float4 px[4];
    #pragma unroll
    for (int u = 0; u < 4; u++) {
        int gr = row0 + rr + 32 * u;
        px[u] = (gr < n) ? ((const float4*)A)[gr * 32 + kq]
                         : make_float4(0.f, 0.f, 0.f, 0.f);
    }
    __syncthreads();   // sc_s/sh_s + ws ready

    #pragma unroll
    for (int kc = 0; kc < 4; kc++) {
        int buf = kc & 1;
        #pragma unroll
        for (int u = 0; u < 4; u++) {
            int f = kc * 32 + kq * 4;
            float v0 = fmaxf(fmaf(px[u].x, sc_s[f + 0], sh_s[f + 0]), 0.0f);
            float v1 = fmaxf(fmaf(px[u].y, sc_s[f + 1], sh_s[f + 1]), 0.0f);
            float v2 = fmaxf(fmaf(px[u].z, sc_s[f + 2], sh_s[f + 2]), 0.0f);
            float v3 = fmaxf(fmaf(px[u].w, sc_s[f + 3], sh_s[f + 3]), 0.0f);
            xs[buf][rr + 32 * u][kq * 2]     = pack_half2(v0, v1);
            xs[buf][rr + 32 * u][kq * 2 + 1] = pack_half2(v2, v3);
        }
        if (kc < 3) {
            #pragma unroll
            for (int u = 0; u < 4; u++) {
                int gr = row0 + rr + 32 * u;
                px[u] = (gr < n) ? ((const float4*)A)[gr * 32 + (kc + 1) * 8 + kq]
                                 : make_float4(0.f, 0.f, 0.f, 0.f);
            }
        }
        __syncthreads();

        #pragma unroll
        for (int ks2 = 0; ks2 < 16; ks2 += 8) {
            unsigned a[4], b[8][2];
            {
                int r0 = rbase + gid;
                a[0] = xs[buf][r0][ks2 + tig];
                a[1] = xs[buf][r0 + 8][ks2 + tig];
                a[2] = xs[buf][r0][ks2 + tig + 4];
                a[3] = xs[buf][r0 + 8][ks2 + tig + 4];
            }
            #pragma unroll
            for (int nt = 0; nt < 8; nt++) {
                int c = 8 * nt + gid;
                b[nt][0] = ws[c][kc * 16 + ks2 + tig];
                b[nt][1] = ws[c][kc * 16 + ks2 + tig + 4];
            }
            #pragma unroll
            for (int nt = 0; nt < 8; nt++)
                mma_f16(acc[nt], a, b[nt]);
        }
    }

    __half2* H2 = (__half2*)g_H2h;
    int r_lo = row0 + rbase + gid;
    int r_hi = r_lo + 8;
    float dlo = (r_lo < n) ? g_dis[r_lo] : 0.0f;
    float dhi = (r_hi < n) ? g_dis[r_hi] : 0.0f;
    #pragma unroll
    for (int nt = 0; nt < 8; nt++) {
        int c = 8 * nt + 2 * tig;
        if (r_lo < n)
            H2[r_lo * 32 + (c >> 1)] =
                __floats2half2_rn(acc[nt][0] * dlo, acc[nt][1] * dlo);
        if (r_hi < n)
            H2[r_hi * 32 + (c >> 1)] =
                __floats2half2_rn(acc[nt][2] * dhi, acc[nt][3] * dhi);
    }
}

// ---------------------------------------------------------------------------
// layer-2 pull aggregation: quarter-warp per node, fp16 gather, writes d_out.
// Restores zeroed state (g_sums, g_degi) for the next graph replay.
// ---------------------------------------------------------------------------
__global__ void __launch_bounds__(256) k_agg2(const float* __restrict__ b2, int n,
                                              float4* __restrict__ out) {
    int t = threadIdx.x;
    if (blockIdx.x == 0 && t < 2 * F1) g_sums[t] = 0.0f;  // restore for replay
    int i = blockIdx.x * 32 + (t >> 3);
    int q = t & 7;
    if (i >= n) return;
    int start = g_row[i];
    int deg   = g_degi[i];
    if (q == 0) g_degi[i] = 0;         // restore for next replay (read above)
    int endj  = start + deg;
    float acc[8] = {0, 0, 0, 0, 0, 0, 0, 0};
    acc_u4(acc, g_H2h[i * 8 + q]);     // self-loop
    int j = start;
    for (; j + 3 < endj; j += 4) {
        int s0 = __ldg(&g_csr[j]),     s1 = __ldg(&g_csr[j + 1]);
        int s2 = __ldg(&g_csr[j + 2]), s3 = __ldg(&g_csr[j + 3]);
        uint4 u0 = g_H2h[s0 * 8 + q];
        uint4 u1 = g_H2h[s1 * 8 + q];
        uint4 u2 = g_H2h[s2 * 8 + q];
        uint4 u3 = g_H2h[s3 * 8 + q];
        acc_u4(acc, u0); acc_u4(acc, u1); acc_u4(acc, u2); acc_u4(acc, u3);
    }
    for (; j < endj; j++) acc_u4(acc, g_H2h[__ldg(&g_csr[j]) * 8 + q]);

    float di = g_dis[i];
    float4 b0 = ((const float4*)b2)[2 * q];
    float4 b1v = ((const float4*)b2)[2 * q + 1];
    out[i * 16 + 2 * q] =
        make_float4(fmaf(acc[0], di, b0.x), fmaf(acc[1], di, b0.y),
                    fmaf(acc[2], di, b0.z), fmaf(acc[3], di, b0.w));
    out[i * 16 + 2 * q + 1] =
        make_float4(fmaf(acc[4], di, b1v.x), fmaf(acc[5], di, b1v.y),
                    fmaf(acc[6], di, b1v.z), fmaf(acc[7], di, b1v.w));
}

// ---------------------------------------------------------------------------
extern "C" void kernel_launch(void* const* d_in, const int* in_sizes, int n_in,
                              void* d_out, int out_size) {
    const float* x     = (const float*)d_in[0];
    const int*   ei    = (const int*)d_in[1];
    const float* W1    = (const float*)d_in[2];
    const float* b1    = (const float*)d_in[3];
    const float* gamma = (const float*)d_in[4];
    const float* beta  = (const float*)d_in[5];
    const float* W2    = (const float*)d_in[6];
    const float* b2    = (const float*)d_in[7];

    int n = in_sizes[0] / F1;       // 100000
    int e = in_sizes[1] / 2;        // 1600000
    int nb = (n + SCAN_B - 1) / SCAN_B;

    // one-time side stream + events (created on first call, outside capture;
    // reused inside the captured graph as a fork/join)
    static cudaStream_t s2 = [] {
        cudaStream_t s; cudaStreamCreateWithFlags(&s, cudaStreamNonBlocking); return s;
    }();
    static cudaEvent_t ev_fork = [] {
        cudaEvent_t ev; cudaEventCreateWithFlags(&ev, cudaEventDisableTiming); return ev;
    }();
    static cudaEvent_t ev_join = [] {
        cudaEvent_t ev; cudaEventCreateWithFlags(&ev, cudaEventDisableTiming); return ev;
    }();

    // fork: GEMM1 (depends only on x, W1) runs on s2 concurrently with the
    // CSR build chain on the default stream.
    cudaEventRecord(ev_fork, 0);
    cudaStreamWaitEvent(s2, ev_fork, 0);
    k_gemm1<<<(n + 127) / 128, 256, 0, s2>>>(x, W1, n);
    cudaEventRecord(ev_join, s2);

    // CSR build on default stream (overlaps with gemm1)
    k_deg_count<<<(e + 255) / 256, 256>>>(ei, W2, e);
    k_scan_block<<<nb, SCAN_B>>>(n);
    k_scan_fin<<<nb, SCAN_B>>>(n, nb);
    k_csr_fill<<<(e + 255) / 256, 256>>>(ei, e);

    // join: agg1 needs both CSR (default) and H1h (s2)
    cudaStreamWaitEvent(0, ev_join, 0);
    k_agg1<<<(n + 15) / 16, 256>>>(b1, n);

    // BN stats
    k_bnstats<<<BN_GRID, 128>>>(n);

    // layer 2 (BN finalize folded into gemm2 prologue)
    k_gemm2<<<(n + 127) / 128, 256>>>(gamma, beta, n);
    k_agg2<<<(n + 31) / 32, 256>>>(b2, n, (float4*)d_out);
}

// round 16
// speedup vs baseline: 1.2503x; 1.0350x over previous
#include <cuda_runtime.h>
#include <cuda_fp16.h>

#define NMAX 100000
#define EMAX 1600000
#define F1 128
#define F2 64
#define BN_EPS 1e-5f
#define SCAN_B 1024
#define BN_GRID 1024

// ---- scratch (device globals; zero-initialized at load; no allocation) ----
__device__ float  g_dis[NMAX];             // rsqrt(degree)
__device__ int    g_degi[NMAX];            // in-degree (zero-restored by agg2)
__device__ int    g_row[NMAX];             // CSR row start
__device__ int    g_epos[EMAX];            // per-edge rank within destination
__device__ int    g_rowtmp[NMAX];          // block-local exclusive scan
__device__ int    g_bsum[128];             // scan block sums
__device__ int    g_csr[EMAX];             // src indices grouped by dst
__device__ uint4  g_H1h[NMAX * 16];        // fp16 (x@W1^T) UNSCALED   [N,128]
__device__ uint4  g_A1h[NMAX * 16];        // fp16 layer-1 aggregated  [N,128]
__device__ uint4  g_H2h[NMAX * 8];         // fp16 dis*(relu(bn)@W2^T) [N,64]
__device__ float  g_sums[2 * F1];          // BN sum/sumsq (zero-restored)
__device__ uint4  g_W2h4[F1 * F2 / 8];     // fp16 W2 row-major [c][k]; 16 uint4/row

// ---- fp16 mma m16n8k16 (row.col, f32 accum) ----
__device__ __forceinline__ void mma_f16(float* d, const unsigned* a, const unsigned* b) {
    asm volatile(
        "mma.sync.aligned.m16n8k16.row.col.f32.f16.f16.f32 "
        "{%0,%1,%2,%3}, {%4,%5,%6,%7}, {%8,%9}, {%0,%1,%2,%3};"
        : "+f"(d[0]), "+f"(d[1]), "+f"(d[2]), "+f"(d[3])
        : "r"(a[0]), "r"(a[1]), "r"(a[2]), "r"(a[3]), "r"(b[0]), "r"(b[1]));
}

__device__ __forceinline__ unsigned pack_half2(float a, float b) {
    __half2 h = __floats2half2_rn(a, b);
    return *reinterpret_cast<unsigned*>(&h);
}

// fp16 row accumulate: acc[0..7] += unpack(u)
__device__ __forceinline__ void acc_u4(float* acc, uint4 u) {
    float2 f0 = __half22float2(*(__half2*)&u.x);
    float2 f1 = __half22float2(*(__half2*)&u.y);
    float2 f2 = __half22float2(*(__half2*)&u.z);
    float2 f3 = __half22float2(*(__half2*)&u.w);
    acc[0] += f0.x; acc[1] += f0.y;
    acc[2] += f1.x; acc[3] += f1.y;
    acc[4] += f2.x; acc[5] += f2.y;
    acc[6] += f3.x; acc[7] += f3.y;
}

// fp16 row fma: acc[0..7] += s * unpack(u)
__device__ __forceinline__ void fma_u4(float* acc, uint4 u, float s) {
    float2 f0 = __half22float2(*(__half2*)&u.x);
    float2 f1 = __half22float2(*(__half2*)&u.y);
    float2 f2 = __half22float2(*(__half2*)&u.z);
    float2 f3 = __half22float2(*(__half2*)&u.w);
    acc[0] = fmaf(f0.x, s, acc[0]); acc[1] = fmaf(f0.y, s, acc[1]);
    acc[2] = fmaf(f1.x, s, acc[2]); acc[3] = fmaf(f1.y, s, acc[3]);
    acc[4] = fmaf(f2.x, s, acc[4]); acc[5] = fmaf(f2.y, s, acc[5]);
    acc[6] = fmaf(f3.x, s, acc[6]); acc[7] = fmaf(f3.y, s, acc[7]);
}

// ---------------------------------------------------------------------------
// degree count + per-edge rank; W2 -> fp16 (W1 handled inside gemm1)
// ---------------------------------------------------------------------------
__global__ void k_deg_count(const int* __restrict__ ei,
                            const float* __restrict__ W2, int e_cnt) {
    int e = blockIdx.x * blockDim.x + threadIdx.x;
    if (e < F1 * F2) ((__half*)g_W2h4)[e] = __float2half_rn(W2[e]);
    if (e < e_cnt) {
        int d = ei[e_cnt + e];
        g_epos[e] = atomicAdd(&g_degi[d], 1);
    }
}

// ---------------------------------------------------------------------------
// scan (2 stages, proven): block-exclusive -> finalize
// ---------------------------------------------------------------------------
__global__ void __launch_bounds__(SCAN_B) k_scan_block(int n) {
    __shared__ int s[SCAN_B];
    int t = threadIdx.x;
    int i = blockIdx.x * SCAN_B + t;
    int v = (i < n) ? g_degi[i] : 0;
    s[t] = v;
    __syncthreads();
    for (int off = 1; off < SCAN_B; off <<= 1) {
        int a = (t >= off) ? s[t - off] : 0;
        __syncthreads();
        s[t] += a;
        __syncthreads();
    }
    if (i < n) g_rowtmp[i] = s[t] - v;
    if (t == SCAN_B - 1) g_bsum[blockIdx.x] = s[t];
}

__global__ void __launch_bounds__(SCAN_B) k_scan_fin(int n, int nb) {
    __shared__ int wsum[32];
    int t = threadIdx.x;
    int v = (t < nb && t < (int)blockIdx.x) ? g_bsum[t] : 0;
    for (int o = 16; o; o >>= 1) v += __shfl_down_sync(0xffffffffu, v, o);
    if ((t & 31) == 0) wsum[t >> 5] = v;
    __syncthreads();
    if (t < 32) {
        int s2 = wsum[t];
        for (int o = 16; o; o >>= 1) s2 += __shfl_down_sync(0xffffffffu, s2, o);
        if (t == 0) wsum[0] = s2;
    }
    __syncthreads();
    int off = wsum[0];
    int i = blockIdx.x * SCAN_B + t;
    if (i < n) {
        g_row[i] = g_rowtmp[i] + off;
        g_dis[i] = rsqrtf((float)(g_degi[i] + 1));
    }
}

// atomic-free CSR fill using precomputed ranks
__global__ void k_csr_fill(const int* __restrict__ ei, int e_cnt) {
    int e = blockIdx.x * blockDim.x + threadIdx.x;
    if (e < e_cnt) {
        int s = ei[e];
        int d = ei[e_cnt + e];
        g_csr[g_row[d] + g_epos[e]] = s;
    }
}

// ---------------------------------------------------------------------------
// GEMM1 (fp16 mma, pipelined, CSR-independent): H1h = fp16(x @ W1^T)
// W1 converted fp32->fp16 at staging. Full W1 staged once (stride 68);
// x double-buffered w/ register prefetch.
// ---------------------------------------------------------------------------
__global__ void __launch_bounds__(256) k_gemm1(const float* __restrict__ x,
                                               const float* __restrict__ W1, int n) {
    __shared__ unsigned xs[2][128][20];
    __shared__ unsigned ws[128][68];
    int t = threadIdx.x;
    int w = t >> 5, lane = t & 31;
    int gid = lane >> 2, tig = lane & 3;
    int rbase = (w >> 1) * 32;
    int cbase = (w & 1) * 64;
    int row0 = blockIdx.x * 128;
    int rr = t >> 3, kq = t & 7;

    #pragma unroll
    for (int i = t; i < 4096; i += 256) {
        int c = i >> 5, kf = i & 31;
        float4 v = ((const float4*)W1)[c * 32 + kf];
        ws[c][kf * 2]     = pack_half2(v.x, v.y);
        ws[c][kf * 2 + 1] = pack_half2(v.z, v.w);
    }

    float acc[2][8][4];
    #pragma unroll
    for (int m = 0; m < 2; m++)
        #pragma unroll
        for (int nt = 0; nt < 8; nt++)
            #pragma unroll
            for (int j = 0; j < 4; j++) acc[m][nt][j] = 0.0f;

    float4 px[4];
    #pragma unroll
    for (int u = 0; u < 4; u++) {
        int gr = row0 + rr + 32 * u;
        px[u] = (gr < n) ? ((const float4*)x)[gr * 32 + kq]
                         : make_float4(0.f, 0.f, 0.f, 0.f);
    }

    #pragma unroll
    for (int kc = 0; kc < 4; kc++) {
        int buf = kc & 1;
        #pragma unroll
        for (int u = 0; u < 4; u++) {
            xs[buf][rr + 32 * u][kq * 2]     = pack_half2(px[u].x, px[u].y);
            xs[buf][rr + 32 * u][kq * 2 + 1] = pack_half2(px[u].z, px[u].w);
        }
        if (kc < 3) {
            #pragma unroll
            for (int u = 0; u < 4; u++) {
                int gr = row0 + rr + 32 * u;
                px[u] = (gr < n) ? ((const float4*)x)[gr * 32 + (kc + 1) * 8 + kq]
                                 : make_float4(0.f, 0.f, 0.f, 0.f);
            }
        }
        __syncthreads();

        #pragma unroll
        for (int ks2 = 0; ks2 < 16; ks2 += 8) {
            unsigned a[2][4], b[8][2];
            #pragma unroll
            for (int m = 0; m < 2; m++) {
                int r0 = rbase + 16 * m + gid;
                a[m][0] = xs[buf][r0][ks2 + tig];
                a[m][1] = xs[buf][r0 + 8][ks2 + tig];
                a[m][2] = xs[buf][r0][ks2 + tig + 4];
                a[m][3] = xs[buf][r0 + 8][ks2 + tig + 4];
            }
            #pragma unroll
            for (int nt = 0; nt < 8; nt++) {
                int c = cbase + 8 * nt + gid;
                b[nt][0] = ws[c][kc * 16 + ks2 + tig];
                b[nt][1] = ws[c][kc * 16 + ks2 + tig + 4];
            }
            #pragma unroll
            for (int m = 0; m < 2; m++)
                #pragma unroll
                for (int nt = 0; nt < 8; nt++)
                    mma_f16(acc[m][nt], a[m], b[nt]);
        }
    }

    __half2* H1 = (__half2*)g_H1h;
    #pragma unroll
    for (int m = 0; m < 2; m++) {
        int r_lo = row0 + rbase + 16 * m + gid;
        int r_hi = r_lo + 8;
        #pragma unroll
        for (int nt = 0; nt < 8; nt++) {
            int c = cbase + 8 * nt + 2 * tig;
            if (r_lo < n)
                H1[r_lo * 64 + (c >> 1)] =
                    __floats2half2_rn(acc[m][nt][0], acc[m][nt][1]);
            if (r_hi < n)
                H1[r_hi * 64 + (c >> 1)] =
                    __floats2half2_rn(acc[m][nt][2], acc[m][nt][3]);
        }
    }
}

// ---------------------------------------------------------------------------
// layer-1 pull aggregation: half-warp per node, per-edge dis[s] scaling,
// fp32 accumulate, fp16 store.
// a1[i] = fp16(dis[i]*(dis[i]*H1[i] + sum_s dis[s]*H1[s]) + b1)
// ---------------------------------------------------------------------------
__global__ void __launch_bounds__(256) k_agg1(const float* __restrict__ b1, int n) {
    int t = threadIdx.x;
    int i = blockIdx.x * 16 + (t >> 4);
    int q = t & 15;
    if (i >= n) return;
    int start = g_row[i];
    int deg   = g_degi[i];
    int endj  = start + deg;
    float di = g_dis[i];
    float acc[8] = {0, 0, 0, 0, 0, 0, 0, 0};
    fma_u4(acc, g_H1h[i * 16 + q], di);          // self-loop
    int j = start;
    for (; j + 3 < endj; j += 4) {
        int s0 = __ldg(&g_csr[j]),     s1 = __ldg(&g_csr[j + 1]);
        int s2 = __ldg(&g_csr[j + 2]), s3 = __ldg(&g_csr[j + 3]);
        float d0 = __ldg(&g_dis[s0]), d1 = __ldg(&g_dis[s1]);
        float d2 = __ldg(&g_dis[s2]), d3 = __ldg(&g_dis[s3]);
        uint4 u0 = g_H1h[s0 * 16 + q];
        uint4 u1 = g_H1h[s1 * 16 + q];
        uint4 u2 = g_H1h[s2 * 16 + q];
        uint4 u3 = g_H1h[s3 * 16 + q];
        fma_u4(acc, u0, d0); fma_u4(acc, u1, d1);
        fma_u4(acc, u2, d2); fma_u4(acc, u3, d3);
    }
    for (; j < endj; j++) {
        int s = __ldg(&g_csr[j]);
        fma_u4(acc, g_H1h[s * 16 + q], __ldg(&g_dis[s]));
    }

    float4 b0 = ((const float4*)b1)[2 * q];
    float4 b1v = ((const float4*)b1)[2 * q + 1];
    uint4 o;
    o.x = pack_half2(fmaf(acc[0], di, b0.x),  fmaf(acc[1], di, b0.y));
    o.y = pack_half2(fmaf(acc[2], di, b0.z),  fmaf(acc[3], di, b0.w));
    o.z = pack_half2(fmaf(acc[4], di, b1v.x), fmaf(acc[5], di, b1v.y));
    o.w = pack_half2(fmaf(acc[6], di, b1v.z), fmaf(acc[7], di, b1v.w));
    g_A1h[i * 16 + q] = o;
}

// ---------------------------------------------------------------------------
// BN statistics over fp16 A1h (L2-resident), 4-deep MLP
// ---------------------------------------------------------------------------
__global__ void k_bnstats(int n) {
    const __half* A = (const __half*)g_A1h;
    int c = threadIdx.x;  // 128
    float s = 0.0f, s2 = 0.0f;
    int r = blockIdx.x;
    for (; r + 3 * BN_GRID < n; r += 4 * BN_GRID) {
        float v0 = __half2float(A[(r) * F1 + c]);
        float v1 = __half2float(A[(r + BN_GRID) * F1 + c]);
        float v2 = __half2float(A[(r + 2 * BN_GRID) * F1 + c]);
        float v3 = __half2float(A[(r + 3 * BN_GRID) * F1 + c]);
        s += v0 + v1 + v2 + v3;
        s2 = fmaf(v0, v0, s2); s2 = fmaf(v1, v1, s2);
        s2 = fmaf(v2, v2, s2); s2 = fmaf(v3, v3, s2);
    }
    for (; r < n; r += BN_GRID) {
        float v = __half2float(A[r * F1 + c]);
        s += v;
        s2 = fmaf(v, v, s2);
    }
    atomicAdd(&g_sums[c], s);
    atomicAdd(&g_sums[F1 + c], s2);
}

// ---------------------------------------------------------------------------
// GEMM2 (fp16 mma, pipelined): H2h = fp16(dis .* (relu(bn(A1h)) @ W2^T))
// Full W2 staged once; A1h (fp16) double-buffered: 2 uint4/thread prefetch,
// BN+ReLU applied at staging; BN finalize in prologue.
// ---------------------------------------------------------------------------
__global__ void __launch_bounds__(256) k_gemm2(const float* __restrict__ gamma,
                                               const float* __restrict__ beta, int n) {
    __shared__ unsigned xs[2][128][20];
    __shared__ unsigned ws[64][68];
    __shared__ float sc_s[F1];
    __shared__ float sh_s[F1];
    int t = threadIdx.x;
    int w = t >> 5, lane = t & 31;
    int gid = lane >> 2, tig = lane & 3;
    int rbase = w * 16;
    int row0 = blockIdx.x * 128;
    int rr = t >> 2, qq = t & 3;     // staging: rows rr, rr+64; uint4 col qq

    #pragma unroll
    for (int i = t; i < 1024; i += 256) {
        int c = i >> 4, q = i & 15;
        *(uint4*)&ws[c][q * 4] = g_W2h4[c * 16 + q];
    }
    if (t < F1) {
        float inv_n = 1.0f / (float)n;
        float mean = g_sums[t] * inv_n;
        float var = g_sums[F1 + t] * inv_n - mean * mean;
        float inv = rsqrtf(var + BN_EPS);
        float sc = gamma[t] * inv;
        sc_s[t] = sc;
        sh_s[t] = beta[t] - mean * sc;
    }

    float acc[8][4];
    #pragma unroll
    for (int nt = 0; nt < 8; nt++)
        #pragma unroll
        for (int j = 0; j < 4; j++) acc[nt][j] = 0.0f;

    // prefetch chunk 0 (2 uint4 per thread)
    uint4 px[2];
    #pragma unroll
    for (int u = 0; u < 2; u++) {
        int gr = row0 + rr + 64 * u;
        px[u] = (gr < n) ? g_A1h[gr * 16 + qq] : make_uint4(0u, 0u, 0u, 0u);
    }
    __syncthreads();   // sc_s/sh_s + ws ready

    #pragma unroll
    for (int kc = 0; kc < 4; kc++) {
        int buf = kc & 1;
        // stage: unpack fp16 -> bn+relu -> repack
        #pragma unroll
        for (int u = 0; u < 2; u++) {
            int r = rr + 64 * u;
            int f = kc * 32 + 8 * qq;
            float2 f0 = __half22float2(*(__half2*)&px[u].x);
            float2 f1 = __half22float2(*(__half2*)&px[u].y);
            float2 f2 = __half22float2(*(__half2*)&px[u].z);
            float2 f3 = __half22float2(*(__half2*)&px[u].w);
            float v0 = fmaxf(fmaf(f0.x, sc_s[f + 0], sh_s[f + 0]), 0.0f);
            float v1 = fmaxf(fmaf(f0.y, sc_s[f + 1], sh_s[f + 1]), 0.0f);
            float v2 = fmaxf(fmaf(f1.x, sc_s[f + 2], sh_s[f + 2]), 0.0f);
            float v3 = fmaxf(fmaf(f1.y, sc_s[f + 3], sh_s[f + 3]), 0.0f);
            float v4 = fmaxf(fmaf(f2.x, sc_s[f + 4], sh_s[f + 4]), 0.0f);
            float v5 = fmaxf(fmaf(f2.y, sc_s[f + 5], sh_s[f + 5]), 0.0f);
            float v6 = fmaxf(fmaf(f3.x, sc_s[f + 6], sh_s[f + 6]), 0.0f);
            float v7 = fmaxf(fmaf(f3.y, sc_s[f + 7], sh_s[f + 7]), 0.0f);
            xs[buf][r][qq * 4 + 0] = pack_half2(v0, v1);
            xs[buf][r][qq * 4 + 1] = pack_half2(v2, v3);
            xs[buf][r][qq * 4 + 2] = pack_half2(v4, v5);
            xs[buf][r][qq * 4 + 3] = pack_half2(v6, v7);
        }
        if (kc < 3) {
            #pragma unroll
            for (int u = 0; u < 2; u++) {
                int gr = row0 + rr + 64 * u;
                px[u] = (gr < n) ? g_A1h[gr * 16 + (kc + 1) * 4 + qq]
                                 : make_uint4(0u, 0u, 0u, 0u);
            }
        }
        __syncthreads();

        #pragma unroll
        for (int ks2 = 0; ks2 < 16; ks2 += 8) {
            unsigned a[4], b[8][2];
            {
                int r0 = rbase + gid;
                a[0] = xs[buf][r0][ks2 + tig];
                a[1] = xs[buf][r0 + 8][ks2 + tig];
                a[2] = xs[buf][r0][ks2 + tig + 4];
                a[3] = xs[buf][r0 + 8][ks2 + tig + 4];
            }
            #pragma unroll
            for (int nt = 0; nt < 8; nt++) {
                int c = 8 * nt + gid;
                b[nt][0] = ws[c][kc * 16 + ks2 + tig];
                b[nt][1] = ws[c][kc * 16 + ks2 + tig + 4];
            }
            #pragma unroll
            for (int nt = 0; nt < 8; nt++)
                mma_f16(acc[nt], a, b[nt]);
        }
    }

    __half2* H2 = (__half2*)g_H2h;
    int r_lo = row0 + rbase + gid;
    int r_hi = r_lo + 8;
    float dlo = (r_lo < n) ? g_dis[r_lo] : 0.0f;
    float dhi = (r_hi < n) ? g_dis[r_hi] : 0.0f;
    #pragma unroll
    for (int nt = 0; nt < 8; nt++) {
        int c = 8 * nt + 2 * tig;
        if (r_lo < n)
            H2[r_lo * 32 + (c >> 1)] =
                __floats2half2_rn(acc[nt][0] * dlo, acc[nt][1] * dlo);
        if (r_hi < n)
            H2[r_hi * 32 + (c >> 1)] =
                __floats2half2_rn(acc[nt][2] * dhi, acc[nt][3] * dhi);
    }
}

// ---------------------------------------------------------------------------
// layer-2 pull aggregation: quarter-warp per node, fp16 gather, writes d_out.
// Restores zeroed state (g_sums, g_degi) for the next graph replay.
// ---------------------------------------------------------------------------
__global__ void __launch_bounds__(256) k_agg2(const float* __restrict__ b2, int n,
                                              float4* __restrict__ out) {
    int t = threadIdx.x;
    if (blockIdx.x == 0 && t < 2 * F1) g_sums[t] = 0.0f;  // restore for replay
    int i = blockIdx.x * 32 + (t >> 3);
    int q = t & 7;
    if (i >= n) return;
    int start = g_row[i];
    int deg   = g_degi[i];
    if (q == 0) g_degi[i] = 0;         // restore for next replay (read above)
    int endj  = start + deg;
    float acc[8] = {0, 0, 0, 0, 0, 0, 0, 0};
    acc_u4(acc, g_H2h[i * 8 + q]);     // self-loop
    int j = start;
    for (; j + 3 < endj; j += 4) {
        int s0 = __ldg(&g_csr[j]),     s1 = __ldg(&g_csr[j + 1]);
        int s2 = __ldg(&g_csr[j + 2]), s3 = __ldg(&g_csr[j + 3]);
        uint4 u0 = g_H2h[s0 * 8 + q];
        uint4 u1 = g_H2h[s1 * 8 + q];
        uint4 u2 = g_H2h[s2 * 8 + q];
        uint4 u3 = g_H2h[s3 * 8 + q];
        acc_u4(acc, u0); acc_u4(acc, u1); acc_u4(acc, u2); acc_u4(acc, u3);
    }
    for (; j < endj; j++) acc_u4(acc, g_H2h[__ldg(&g_csr[j]) * 8 + q]);

    float di = g_dis[i];
    float4 b0 = ((const float4*)b2)[2 * q];
    float4 b1v = ((const float4*)b2)[2 * q + 1];
    out[i * 16 + 2 * q] =
        make_float4(fmaf(acc[0], di, b0.x), fmaf(acc[1], di, b0.y),
                    fmaf(acc[2], di, b0.z), fmaf(acc[3], di, b0.w));
    out[i * 16 + 2 * q + 1] =
        make_float4(fmaf(acc[4], di, b1v.x), fmaf(acc[5], di, b1v.y),
                    fmaf(acc[6], di, b1v.z), fmaf(acc[7], di, b1v.w));
}

// ---------------------------------------------------------------------------
extern "C" void kernel_launch(void* const* d_in, const int* in_sizes, int n_in,
                              void* d_out, int out_size) {
    const float* x     = (const float*)d_in[0];
    const int*   ei    = (const int*)d_in[1];
    const float* W1    = (const float*)d_in[2];
    const float* b1    = (const float*)d_in[3];
    const float* gamma = (const float*)d_in[4];
    const float* beta  = (const float*)d_in[5];
    const float* W2    = (const float*)d_in[6];
    const float* b2    = (const float*)d_in[7];

    int n = in_sizes[0] / F1;       // 100000
    int e = in_sizes[1] / 2;        // 1600000
    int nb = (n + SCAN_B - 1) / SCAN_B;

    static cudaStream_t s2 = [] {
        cudaStream_t s; cudaStreamCreateWithFlags(&s, cudaStreamNonBlocking); return s;
    }();
    static cudaEvent_t ev_fork = [] {
        cudaEvent_t ev; cudaEventCreateWithFlags(&ev, cudaEventDisableTiming); return ev;
    }();
    static cudaEvent_t ev_join = [] {
        cudaEvent_t ev; cudaEventCreateWithFlags(&ev, cudaEventDisableTiming); return ev;
    }();

    // fork: GEMM1 (x, W1 only) on s2, concurrent with CSR build
    cudaEventRecord(ev_fork, 0);
    cudaStreamWaitEvent(s2, ev_fork, 0);
    k_gemm1<<<(n + 127) / 128, 256, 0, s2>>>(x, W1, n);
    cudaEventRecord(ev_join, s2);

    // CSR build on default stream (overlaps with gemm1)
    k_deg_count<<<(e + 255) / 256, 256>>>(ei, W2, e);
    k_scan_block<<<nb, SCAN_B>>>(n);
    k_scan_fin<<<nb, SCAN_B>>>(n, nb);
    k_csr_fill<<<(e + 255) / 256, 256>>>(ei, e);

    // join: agg1 needs both CSR (default) and H1h (s2)
    cudaStreamWaitEvent(0, ev_join, 0);
    k_agg1<<<(n + 15) / 16, 256>>>(b1, n);

    // BN stats
    k_bnstats<<<BN_GRID, 128>>>(n);

    // layer 2 (BN finalize folded into gemm2 prologue)
    k_gemm2<<<(n + 127) / 128, 256>>>(gamma, beta, n);
    k_agg2<<<(n + 31) / 32, 256>>>(b2, n, (float4*)d_out);
}

// round 17
// speedup vs baseline: 1.2520x; 1.0013x over previous
#include <cuda_runtime.h>
#include <cuda_fp16.h>

#define NMAX 100000
#define EMAX 1600000
#define F1 128
#define F2 64
#define BN_EPS 1e-5f
#define SCAN_B 1024
#define BN_GRID 1024

// ---- scratch (device globals; zero-initialized at load; no allocation) ----
__device__ float  g_dis[NMAX];             // rsqrt(degree)
__device__ int    g_degi[NMAX];            // in-degree (zero-restored by agg2)
__device__ int    g_row[NMAX];             // CSR row start
__device__ int    g_epos[EMAX];            // per-edge rank within destination
__device__ int    g_rowtmp[NMAX];          // block-local exclusive scan
__device__ int    g_bsum[128];             // scan block sums
__device__ int    g_csr[EMAX];             // src indices grouped by dst
__device__ uint4  g_H1h[NMAX * 16];        // fp16 (x@W1^T) UNSCALED   [N,128]
__device__ uint4  g_A1h[NMAX * 16];        // fp16 layer-1 aggregated  [N,128]
__device__ uint4  g_H2h[NMAX * 8];         // fp16 dis*(relu(bn)@W2^T) [N,64]
__device__ float  g_sums[2 * F1];          // BN sum/sumsq (zero-restored)
__device__ uint4  g_W2h4[F1 * F2 / 8];     // fp16 W2 row-major [c][k]; 16 uint4/row

// ---- fp16 mma m16n8k16 (row.col, f32 accum) ----
__device__ __forceinline__ void mma_f16(float* d, const unsigned* a, const unsigned* b) {
    asm volatile(
        "mma.sync.aligned.m16n8k16.row.col.f32.f16.f16.f32 "
        "{%0,%1,%2,%3}, {%4,%5,%6,%7}, {%8,%9}, {%0,%1,%2,%3};"
        : "+f"(d[0]), "+f"(d[1]), "+f"(d[2]), "+f"(d[3])
        : "r"(a[0]), "r"(a[1]), "r"(a[2]), "r"(a[3]), "r"(b[0]), "r"(b[1]));
}

__device__ __forceinline__ unsigned pack_half2(float a, float b) {
    __half2 h = __floats2half2_rn(a, b);
    return *reinterpret_cast<unsigned*>(&h);
}

// fp16 row accumulate: acc[0..7] += unpack(u)
__device__ __forceinline__ void acc_u4(float* acc, uint4 u) {
    float2 f0 = __half22float2(*(__half2*)&u.x);
    float2 f1 = __half22float2(*(__half2*)&u.y);
    float2 f2 = __half22float2(*(__half2*)&u.z);
    float2 f3 = __half22float2(*(__half2*)&u.w);
    acc[0] += f0.x; acc[1] += f0.y;
    acc[2] += f1.x; acc[3] += f1.y;
    acc[4] += f2.x; acc[5] += f2.y;
    acc[6] += f3.x; acc[7] += f3.y;
}

// fp16 row fma: acc[0..7] += s * unpack(u)
__device__ __forceinline__ void fma_u4(float* acc, uint4 u, float s) {
    float2 f0 = __half22float2(*(__half2*)&u.x);
    float2 f1 = __half22float2(*(__half2*)&u.y);
    float2 f2 = __half22float2(*(__half2*)&u.z);
    float2 f3 = __half22float2(*(__half2*)&u.w);
    acc[0] = fmaf(f0.x, s, acc[0]); acc[1] = fmaf(f0.y, s, acc[1]);
    acc[2] = fmaf(f1.x, s, acc[2]); acc[3] = fmaf(f1.y, s, acc[3]);
    acc[4] = fmaf(f2.x, s, acc[4]); acc[5] = fmaf(f2.y, s, acc[5]);
    acc[6] = fmaf(f3.x, s, acc[6]); acc[7] = fmaf(f3.y, s, acc[7]);
}

// ---------------------------------------------------------------------------
// degree count + per-edge rank; W2 -> fp16 (W1 handled inside gemm1)
// ---------------------------------------------------------------------------
__global__ void k_deg_count(const int* __restrict__ ei,
                            const float* __restrict__ W2, int e_cnt) {
    int e = blockIdx.x * blockDim.x + threadIdx.x;
    if (e < F1 * F2) ((__half*)g_W2h4)[e] = __float2half_rn(W2[e]);
    if (e < e_cnt) {
        int d = ei[e_cnt + e];
        g_epos[e] = atomicAdd(&g_degi[d], 1);
    }
}

// ---------------------------------------------------------------------------
// scan (2 stages, proven): block-exclusive -> finalize
// ---------------------------------------------------------------------------
__global__ void __launch_bounds__(SCAN_B) k_scan_block(int n) {
    __shared__ int s[SCAN_B];
    int t = threadIdx.x;
    int i = blockIdx.x * SCAN_B + t;
    int v = (i < n) ? g_degi[i] : 0;
    s[t] = v;
    __syncthreads();
    for (int off = 1; off < SCAN_B; off <<= 1) {
        int a = (t >= off) ? s[t - off] : 0;
        __syncthreads();
        s[t] += a;
        __syncthreads();
    }
    if (i < n) g_rowtmp[i] = s[t] - v;
    if (t == SCAN_B - 1) g_bsum[blockIdx.x] = s[t];
}

__global__ void __launch_bounds__(SCAN_B) k_scan_fin(int n, int nb) {
    __shared__ int wsum[32];
    int t = threadIdx.x;
    int v = (t < nb && t < (int)blockIdx.x) ? g_bsum[t] : 0;
    for (int o = 16; o; o >>= 1) v += __shfl_down_sync(0xffffffffu, v, o);
    if ((t & 31) == 0) wsum[t >> 5] = v;
    __syncthreads();
    if (t < 32) {
        int s2 = wsum[t];
        for (int o = 16; o; o >>= 1) s2 += __shfl_down_sync(0xffffffffu, s2, o);
        if (t == 0) wsum[0] = s2;
    }
    __syncthreads();
    int off = wsum[0];
    int i = blockIdx.x * SCAN_B + t;
    if (i < n) {
        g_row[i] = g_rowtmp[i] + off;
        g_dis[i] = rsqrtf((float)(g_degi[i] + 1));
    }
}

// atomic-free CSR fill using precomputed ranks
__global__ void k_csr_fill(const int* __restrict__ ei, int e_cnt) {
    int e = blockIdx.x * blockDim.x + threadIdx.x;
    if (e < e_cnt) {
        int s = ei[e];
        int d = ei[e_cnt + e];
        g_csr[g_row[d] + g_epos[e]] = s;
    }
}

// ---------------------------------------------------------------------------
// GEMM1 (fp16 mma, pipelined, CSR-independent): H1h = fp16(x @ W1^T)
// ---------------------------------------------------------------------------
__global__ void __launch_bounds__(256) k_gemm1(const float* __restrict__ x,
                                               const float* __restrict__ W1, int n) {
    __shared__ unsigned xs[2][128][20];
    __shared__ unsigned ws[128][68];
    int t = threadIdx.x;
    int w = t >> 5, lane = t & 31;
    int gid = lane >> 2, tig = lane & 3;
    int rbase = (w >> 1) * 32;
    int cbase = (w & 1) * 64;
    int row0 = blockIdx.x * 128;
    int rr = t >> 3, kq = t & 7;

    #pragma unroll
    for (int i = t; i < 4096; i += 256) {
        int c = i >> 5, kf = i & 31;
        float4 v = ((const float4*)W1)[c * 32 + kf];
        ws[c][kf * 2]     = pack_half2(v.x, v.y);
        ws[c][kf * 2 + 1] = pack_half2(v.z, v.w);
    }

    float acc[2][8][4];
    #pragma unroll
    for (int m = 0; m < 2; m++)
        #pragma unroll
        for (int nt = 0; nt < 8; nt++)
            #pragma unroll
            for (int j = 0; j < 4; j++) acc[m][nt][j] = 0.0f;

    float4 px[4];
    #pragma unroll
    for (int u = 0; u < 4; u++) {
        int gr = row0 + rr + 32 * u;
        px[u] = (gr < n) ? ((const float4*)x)[gr * 32 + kq]
                         : make_float4(0.f, 0.f, 0.f, 0.f);
    }

    #pragma unroll
    for (int kc = 0; kc < 4; kc++) {
        int buf = kc & 1;
        #pragma unroll
        for (int u = 0; u < 4; u++) {
            xs[buf][rr + 32 * u][kq * 2]     = pack_half2(px[u].x, px[u].y);
            xs[buf][rr + 32 * u][kq * 2 + 1] = pack_half2(px[u].z, px[u].w);
        }
        if (kc < 3) {
            #pragma unroll
            for (int u = 0; u < 4; u++) {
                int gr = row0 + rr + 32 * u;
                px[u] = (gr < n) ? ((const float4*)x)[gr * 32 + (kc + 1) * 8 + kq]
                                 : make_float4(0.f, 0.f, 0.f, 0.f);
            }
        }
        __syncthreads();

        #pragma unroll
        for (int ks2 = 0; ks2 < 16; ks2 += 8) {
            unsigned a[2][4], b[8][2];
            #pragma unroll
            for (int m = 0; m < 2; m++) {
                int r0 = rbase + 16 * m + gid;
                a[m][0] = xs[buf][r0][ks2 + tig];
                a[m][1] = xs[buf][r0 + 8][ks2 + tig];
                a[m][2] = xs[buf][r0][ks2 + tig + 4];
                a[m][3] = xs[buf][r0 + 8][ks2 + tig + 4];
            }
            #pragma unroll
            for (int nt = 0; nt < 8; nt++) {
                int c = cbase + 8 * nt + gid;
                b[nt][0] = ws[c][kc * 16 + ks2 + tig];
                b[nt][1] = ws[c][kc * 16 + ks2 + tig + 4];
            }
            #pragma unroll
            for (int m = 0; m < 2; m++)
                #pragma unroll
                for (int nt = 0; nt < 8; nt++)
                    mma_f16(acc[m][nt], a[m], b[nt]);
        }
    }

    __half2* H1 = (__half2*)g_H1h;
    #pragma unroll
    for (int m = 0; m < 2; m++) {
        int r_lo = row0 + rbase + 16 * m + gid;
        int r_hi = r_lo + 8;
        #pragma unroll
        for (int nt = 0; nt < 8; nt++) {
            int c = cbase + 8 * nt + 2 * tig;
            if (r_lo < n)
                H1[r_lo * 64 + (c >> 1)] =
                    __floats2half2_rn(acc[m][nt][0], acc[m][nt][1]);
            if (r_hi < n)
                H1[r_hi * 64 + (c >> 1)] =
                    __floats2half2_rn(acc[m][nt][2], acc[m][nt][3]);
        }
    }
}

// ---------------------------------------------------------------------------
// layer-1 pull aggregation: half-warp per node, per-edge dis[s] scaling,
// 8-deep MLP unroll, fp32 accumulate, fp16 store.
// ---------------------------------------------------------------------------
__global__ void __launch_bounds__(256) k_agg1(const float* __restrict__ b1, int n) {
    int t = threadIdx.x;
    int i = blockIdx.x * 16 + (t >> 4);
    int q = t & 15;
    if (i >= n) return;
    int start = g_row[i];
    int deg   = g_degi[i];
    int endj  = start + deg;
    float di = g_dis[i];
    float acc[8] = {0, 0, 0, 0, 0, 0, 0, 0};
    fma_u4(acc, g_H1h[i * 16 + q], di);          // self-loop
    int j = start;
    for (; j + 7 < endj; j += 8) {
        int s0 = __ldg(&g_csr[j]),     s1 = __ldg(&g_csr[j + 1]);
        int s2 = __ldg(&g_csr[j + 2]), s3 = __ldg(&g_csr[j + 3]);
        int s4 = __ldg(&g_csr[j + 4]), s5 = __ldg(&g_csr[j + 5]);
        int s6 = __ldg(&g_csr[j + 6]), s7 = __ldg(&g_csr[j + 7]);
        float d0 = __ldg(&g_dis[s0]), d1 = __ldg(&g_dis[s1]);
        float d2 = __ldg(&g_dis[s2]), d3 = __ldg(&g_dis[s3]);
        float d4 = __ldg(&g_dis[s4]), d5 = __ldg(&g_dis[s5]);
        float d6 = __ldg(&g_dis[s6]), d7 = __ldg(&g_dis[s7]);
        uint4 u0 = g_H1h[s0 * 16 + q];
        uint4 u1 = g_H1h[s1 * 16 + q];
        uint4 u2 = g_H1h[s2 * 16 + q];
        uint4 u3 = g_H1h[s3 * 16 + q];
        uint4 u4 = g_H1h[s4 * 16 + q];
        uint4 u5 = g_H1h[s5 * 16 + q];
        uint4 u6 = g_H1h[s6 * 16 + q];
        uint4 u7 = g_H1h[s7 * 16 + q];
        fma_u4(acc, u0, d0); fma_u4(acc, u1, d1);
        fma_u4(acc, u2, d2); fma_u4(acc, u3, d3);
        fma_u4(acc, u4, d4); fma_u4(acc, u5, d5);
        fma_u4(acc, u6, d6); fma_u4(acc, u7, d7);
    }
    if (j + 3 < endj) {
        int s0 = __ldg(&g_csr[j]),     s1 = __ldg(&g_csr[j + 1]);
        int s2 = __ldg(&g_csr[j + 2]), s3 = __ldg(&g_csr[j + 3]);
        float d0 = __ldg(&g_dis[s0]), d1 = __ldg(&g_dis[s1]);
        float d2 = __ldg(&g_dis[s2]), d3 = __ldg(&g_dis[s3]);
        uint4 u0 = g_H1h[s0 * 16 + q];
        uint4 u1 = g_H1h[s1 * 16 + q];
        uint4 u2 = g_H1h[s2 * 16 + q];
        uint4 u3 = g_H1h[s3 * 16 + q];
        fma_u4(acc, u0, d0); fma_u4(acc, u1, d1);
        fma_u4(acc, u2, d2); fma_u4(acc, u3, d3);
        j += 4;
    }
    for (; j < endj; j++) {
        int s = __ldg(&g_csr[j]);
        fma_u4(acc, g_H1h[s * 16 + q], __ldg(&g_dis[s]));
    }

    float4 b0 = ((const float4*)b1)[2 * q];
    float4 b1v = ((const float4*)b1)[2 * q + 1];
    uint4 o;
    o.x = pack_half2(fmaf(acc[0], di, b0.x),  fmaf(acc[1], di, b0.y));
    o.y = pack_half2(fmaf(acc[2], di, b0.z),  fmaf(acc[3], di, b0.w));
    o.z = pack_half2(fmaf(acc[4], di, b1v.x), fmaf(acc[5], di, b1v.y));
    o.w = pack_half2(fmaf(acc[6], di, b1v.z), fmaf(acc[7], di, b1v.w));
    g_A1h[i * 16 + q] = o;
}

// ---------------------------------------------------------------------------
// BN statistics over fp16 A1h (L2-resident), 4-deep MLP
// ---------------------------------------------------------------------------
__global__ void k_bnstats(int n) {
    const __half* A = (const __half*)g_A1h;
    int c = threadIdx.x;  // 128
    float s = 0.0f, s2 = 0.0f;
    int r = blockIdx.x;
    for (; r + 3 * BN_GRID < n; r += 4 * BN_GRID) {
        float v0 = __half2float(A[(r) * F1 + c]);
        float v1 = __half2float(A[(r + BN_GRID) * F1 + c]);
        float v2 = __half2float(A[(r + 2 * BN_GRID) * F1 + c]);
        float v3 = __half2float(A[(r + 3 * BN_GRID) * F1 + c]);
        s += v0 + v1 + v2 + v3;
        s2 = fmaf(v0, v0, s2); s2 = fmaf(v1, v1, s2);
        s2 = fmaf(v2, v2, s2); s2 = fmaf(v3, v3, s2);
    }
    for (; r < n; r += BN_GRID) {
        float v = __half2float(A[r * F1 + c]);
        s += v;
        s2 = fmaf(v, v, s2);
    }
    atomicAdd(&g_sums[c], s);
    atomicAdd(&g_sums[F1 + c], s2);
}

// ---------------------------------------------------------------------------
// GEMM2 (fp16 mma, pipelined): H2h = fp16(dis .* (relu(bn(A1h)) @ W2^T))
// ---------------------------------------------------------------------------
__global__ void __launch_bounds__(256) k_gemm2(const float* __restrict__ gamma,
                                               const float* __restrict__ beta, int n) {
    __shared__ unsigned xs[2][128][20];
    __shared__ unsigned ws[64][68];
    __shared__ float sc_s[F1];
    __shared__ float sh_s[F1];
    int t = threadIdx.x;
    int w = t >> 5, lane = t & 31;
    int gid = lane >> 2, tig = lane & 3;
    int rbase = w * 16;
    int row0 = blockIdx.x * 128;
    int rr = t >> 2, qq = t & 3;

    #pragma unroll
    for (int i = t; i < 1024; i += 256) {
        int c = i >> 4, q = i & 15;
        *(uint4*)&ws[c][q * 4] = g_W2h4[c * 16 + q];
    }
    if (t < F1) {
        float inv_n = 1.0f / (float)n;
        float mean = g_sums[t] * inv_n;
        float var = g_sums[F1 + t] * inv_n - mean * mean;
        float inv = rsqrtf(var + BN_EPS);
        float sc = gamma[t] * inv;
        sc_s[t] = sc;
        sh_s[t] = beta[t] - mean * sc;
    }

    float acc[8][4];
    #pragma unroll
    for (int nt = 0; nt < 8; nt++)
        #pragma unroll
        for (int j = 0; j < 4; j++) acc[nt][j] = 0.0f;

    uint4 px[2];
    #pragma unroll
    for (int u = 0; u < 2; u++) {
        int gr = row0 + rr + 64 * u;
        px[u] = (gr < n) ? g_A1h[gr * 16 + qq] : make_uint4(0u, 0u, 0u, 0u);
    }
    __syncthreads();

    #pragma unroll
    for (int kc = 0; kc < 4; kc++) {
        int buf = kc & 1;
        #pragma unroll
        for (int u = 0; u < 2; u++) {
            int r = rr + 64 * u;
            int f = kc * 32 + 8 * qq;
            float2 f0 = __half22float2(*(__half2*)&px[u].x);
            float2 f1 = __half22float2(*(__half2*)&px[u].y);
            float2 f2 = __half22float2(*(__half2*)&px[u].z);
            float2 f3 = __half22float2(*(__half2*)&px[u].w);
            float v0 = fmaxf(fmaf(f0.x, sc_s[f + 0], sh_s[f + 0]), 0.0f);
            float v1 = fmaxf(fmaf(f0.y, sc_s[f + 1], sh_s[f + 1]), 0.0f);
            float v2 = fmaxf(fmaf(f1.x, sc_s[f + 2], sh_s[f + 2]), 0.0f);
            float v3 = fmaxf(fmaf(f1.y, sc_s[f + 3], sh_s[f + 3]), 0.0f);
            float v4 = fmaxf(fmaf(f2.x, sc_s[f + 4], sh_s[f + 4]), 0.0f);
            float v5 = fmaxf(fmaf(f2.y, sc_s[f + 5], sh_s[f + 5]), 0.0f);
            float v6 = fmaxf(fmaf(f3.x, sc_s[f + 6], sh_s[f + 6]), 0.0f);
            float v7 = fmaxf(fmaf(f3.y, sc_s[f + 7], sh_s[f + 7]), 0.0f);
            xs[buf][r][qq * 4 + 0] = pack_half2(v0, v1);
            xs[buf][r][qq * 4 + 1] = pack_half2(v2, v3);
            xs[buf][r][qq * 4 + 2] = pack_half2(v4, v5);
            xs[buf][r][qq * 4 + 3] = pack_half2(v6, v7);
        }
        if (kc < 3) {
            #pragma unroll
            for (int u = 0; u < 2; u++) {
                int gr = row0 + rr + 64 * u;
                px[u] = (gr < n) ? g_A1h[gr * 16 + (kc + 1) * 4 + qq]
                                 : make_uint4(0u, 0u, 0u, 0u);
            }
        }
        __syncthreads();

        #pragma unroll
        for (int ks2 = 0; ks2 < 16; ks2 += 8) {
            unsigned a[4], b[8][2];
            {
                int r0 = rbase + gid;
                a[0] = xs[buf][r0][ks2 + tig];
                a[1] = xs[buf][r0 + 8][ks2 + tig];
                a[2] = xs[buf][r0][ks2 + tig + 4];
                a[3] = xs[buf][r0 + 8][ks2 + tig + 4];
            }
            #pragma unroll
            for (int nt = 0; nt < 8; nt++) {
                int c = 8 * nt + gid;
                b[nt][0] = ws[c][kc * 16 + ks2 + tig];
                b[nt][1] = ws[c][kc * 16 + ks2 + tig + 4];
            }
            #pragma unroll
            for (int nt = 0; nt < 8; nt++)
                mma_f16(acc[nt], a, b[nt]);
        }
    }

    __half2* H2 = (__half2*)g_H2h;
    int r_lo = row0 + rbase + gid;
    int r_hi = r_lo + 8;
    float dlo = (r_lo < n) ? g_dis[r_lo] : 0.0f;
    float dhi = (r_hi < n) ? g_dis[r_hi] : 0.0f;
    #pragma unroll
    for (int nt = 0; nt < 8; nt++) {
        int c = 8 * nt + 2 * tig;
        if (r_lo < n)
            H2[r_lo * 32 + (c >> 1)] =
                __floats2half2_rn(acc[nt][0] * dlo, acc[nt][1] * dlo);
        if (r_hi < n)
            H2[r_hi * 32 + (c >> 1)] =
                __floats2half2_rn(acc[nt][2] * dhi, acc[nt][3] * dhi);
    }
}

// ---------------------------------------------------------------------------
// layer-2 pull aggregation: quarter-warp per node, 8-deep MLP, writes d_out.
// Restores zeroed state (g_sums, g_degi) for the next graph replay.
// ---------------------------------------------------------------------------
__global__ void __launch_bounds__(256) k_agg2(const float* __restrict__ b2, int n,
                                              float4* __restrict__ out) {
    int t = threadIdx.x;
    if (blockIdx.x == 0 && t < 2 * F1) g_sums[t] = 0.0f;  // restore for replay
    int i = blockIdx.x * 32 + (t >> 3);
    int q = t & 7;
    if (i >= n) return;
    int start = g_row[i];
    int deg   = g_degi[i];
    if (q == 0) g_degi[i] = 0;         // restore for next replay (read above)
    int endj  = start + deg;
    float acc[8] = {0, 0, 0, 0, 0, 0, 0, 0};
    acc_u4(acc, g_H2h[i * 8 + q]);     // self-loop
    int j = start;
    for (; j + 7 < endj; j += 8) {
        int s0 = __ldg(&g_csr[j]),     s1 = __ldg(&g_csr[j + 1]);
        int s2 = __ldg(&g_csr[j + 2]), s3 = __ldg(&g_csr[j + 3]);
        int s4 = __ldg(&g_csr[j + 4]), s5 = __ldg(&g_csr[j + 5]);
        int s6 = __ldg(&g_csr[j + 6]), s7 = __ldg(&g_csr[j + 7]);
        uint4 u0 = g_H2h[s0 * 8 + q];
        uint4 u1 = g_H2h[s1 * 8 + q];
        uint4 u2 = g_H2h[s2 * 8 + q];
        uint4 u3 = g_H2h[s3 * 8 + q];
        uint4 u4 = g_H2h[s4 * 8 + q];
        uint4 u5 = g_H2h[s5 * 8 + q];
        uint4 u6 = g_H2h[s6 * 8 + q];
        uint4 u7 = g_H2h[s7 * 8 + q];
        acc_u4(acc, u0); acc_u4(acc, u1); acc_u4(acc, u2); acc_u4(acc, u3);
        acc_u4(acc, u4); acc_u4(acc, u5); acc_u4(acc, u6); acc_u4(acc, u7);
    }
    if (j + 3 < endj) {
        int s0 = __ldg(&g_csr[j]),     s1 = __ldg(&g_csr[j + 1]);
        int s2 = __ldg(&g_csr[j + 2]), s3 = __ldg(&g_csr[j + 3]);
        uint4 u0 = g_H2h[s0 * 8 + q];
        uint4 u1 = g_H2h[s1 * 8 + q];
        uint4 u2 = g_H2h[s2 * 8 + q];
        uint4 u3 = g_H2h[s3 * 8 + q];
        acc_u4(acc, u0); acc_u4(acc, u1); acc_u4(acc, u2); acc_u4(acc, u3);
        j += 4;
    }
    for (; j < endj; j++) acc_u4(acc, g_H2h[__ldg(&g_csr[j]) * 8 + q]);

    float di = g_dis[i];
    float4 b0 = ((const float4*)b2)[2 * q];
    float4 b1v = ((const float4*)b2)[2 * q + 1];
    out[i * 16 + 2 * q] =
        make_float4(fmaf(acc[0], di, b0.x), fmaf(acc[1], di, b0.y),
                    fmaf(acc[2], di, b0.z), fmaf(acc[3], di, b0.w));
    out[i * 16 + 2 * q + 1] =
        make_float4(fmaf(acc[4], di, b1v.x), fmaf(acc[5], di, b1v.y),
                    fmaf(acc[6], di, b1v.z), fmaf(acc[7], di, b1v.w));
}

// ---------------------------------------------------------------------------
extern "C" void kernel_launch(void* const* d_in, const int* in_sizes, int n_in,
                              void* d_out, int out_size) {
    const float* x     = (const float*)d_in[0];
    const int*   ei    = (const int*)d_in[1];
    const float* W1    = (const float*)d_in[2];
    const float* b1    = (const float*)d_in[3];
    const float* gamma = (const float*)d_in[4];
    const float* beta  = (const float*)d_in[5];
    const float* W2    = (const float*)d_in[6];
    const float* b2    = (const float*)d_in[7];

    int n = in_sizes[0] / F1;       // 100000
    int e = in_sizes[1] / 2;        // 1600000
    int nb = (n + SCAN_B - 1) / SCAN_B;

    static cudaStream_t s2 = [] {
        cudaStream_t s; cudaStreamCreateWithFlags(&s, cudaStreamNonBlocking); return s;
    }();
    static cudaEvent_t ev_fork = [] {
        cudaEvent_t ev; cudaEventCreateWithFlags(&ev, cudaEventDisableTiming); return ev;
    }();
    static cudaEvent_t ev_join = [] {
        cudaEvent_t ev; cudaEventCreateWithFlags(&ev, cudaEventDisableTiming); return ev;
    }();

    // fork: GEMM1 (x, W1 only) on s2, concurrent with CSR build
    cudaEventRecord(ev_fork, 0);
    cudaStreamWaitEvent(s2, ev_fork, 0);
    k_gemm1<<<(n + 127) / 128, 256, 0, s2>>>(x, W1, n);
    cudaEventRecord(ev_join, s2);

    // CSR build on default stream (overlaps with gemm1)
    k_deg_count<<<(e + 255) / 256, 256>>>(ei, W2, e);
    k_scan_block<<<nb, SCAN_B>>>(n);
    k_scan_fin<<<nb, SCAN_B>>>(n, nb);
    k_csr_fill<<<(e + 255) / 256, 256>>>(ei, e);

    // join: agg1 needs both CSR (default) and H1h (s2)
    cudaStreamWaitEvent(0, ev_join, 0);
    k_agg1<<<(n + 15) / 16, 256>>>(b1, n);

    // BN stats
    k_bnstats<<<BN_GRID, 128>>>(n);

    // layer 2 (BN finalize folded into gemm2 prologue)
    k_gemm2<<<(n + 127) / 128, 256>>>(gamma, beta, n);
    k_agg2<<<(n + 31) / 32, 256>>>(b2, n, (float4*)d_out);
}